// round 1
// baseline (speedup 1.0000x reference)
#include <cuda_runtime.h>
#include <cuda_bf16.h>
#include <cstddef>

// Problem constants
#define BATCH 4
#define SEQ   2048
#define CDIM  1024
#define NHEAD 16
#define HDIM  64
#define BT    (BATCH*SEQ)       // 8192
#define QKV_N (3*CDIM)          // 3072

// Scratch (device globals; no allocation allowed)
__device__ float g_q[BATCH*NHEAD*SEQ*HDIM];   // [B,H,T,hd]
__device__ float g_k[BATCH*NHEAD*SEQ*HDIM];
__device__ float g_v[BATCH*NHEAD*SEQ*HDIM];
__device__ float g_y[BT*CDIM];                // [B,T,C]

// ---------------------------------------------------------------------------
// Tiled fp32 GEMM: C[M,N] = A[M,K] @ B[K,N]
// 128x128 tile, BK=16, 256 threads, 8x8 per-thread register block.
// EPI=0: plain write to C (ldc=N). EPI=1: scatter into g_q/g_k/g_v.
// ---------------------------------------------------------------------------
template<int EPI>
__global__ __launch_bounds__(256) void gemm128(
    const float* __restrict__ A, const float* __restrict__ B,
    float* __restrict__ C, int N, int K, int lda, int ldb)
{
    const int BK = 16;
    __shared__ float As[BK][132];   // transposed A tile, padded
    __shared__ float Bs[BK][128];

    int t  = threadIdx.x;
    int tx = t & 15;
    int ty = t >> 4;
    int m0 = blockIdx.y * 128;
    int n0 = blockIdx.x * 128;

    float acc[8][8];
    #pragma unroll
    for (int i = 0; i < 8; ++i)
        #pragma unroll
        for (int j = 0; j < 8; ++j) acc[i][j] = 0.f;

    int ar = t >> 2;          // 0..63
    int ac = (t & 3) * 4;     // 0,4,8,12
    int br = t >> 5;          // 0..7
    int bc = (t & 31) * 4;    // 0..124

    for (int k0 = 0; k0 < K; k0 += BK) {
        #pragma unroll
        for (int rr = 0; rr < 2; ++rr) {
            int r = ar + rr * 64;
            float4 va = *(const float4*)(A + (size_t)(m0 + r) * lda + k0 + ac);
            As[ac + 0][r] = va.x;
            As[ac + 1][r] = va.y;
            As[ac + 2][r] = va.z;
            As[ac + 3][r] = va.w;
        }
        #pragma unroll
        for (int rr = 0; rr < 2; ++rr) {
            int r = br + rr * 8;
            *(float4*)(&Bs[r][bc]) =
                *(const float4*)(B + (size_t)(k0 + r) * ldb + n0 + bc);
        }
        __syncthreads();

        #pragma unroll
        for (int kk = 0; kk < BK; ++kk) {
            float a[8], b[8];
            *(float4*)(a)     = *(const float4*)(&As[kk][ty * 8]);
            *(float4*)(a + 4) = *(const float4*)(&As[kk][ty * 8 + 4]);
            *(float4*)(b)     = *(const float4*)(&Bs[kk][tx * 8]);
            *(float4*)(b + 4) = *(const float4*)(&Bs[kk][tx * 8 + 4]);
            #pragma unroll
            for (int i = 0; i < 8; ++i)
                #pragma unroll
                for (int j = 0; j < 8; ++j)
                    acc[i][j] += a[i] * b[j];
        }
        __syncthreads();
    }

    if (EPI == 0) {
        // plain: C row-major, ldc = N
        #pragma unroll
        for (int i = 0; i < 8; ++i) {
            float* cp = C + (size_t)(m0 + ty * 8 + i) * N + n0 + tx * 8;
            *(float4*)(cp)     = *(float4*)(&acc[i][0]);
            *(float4*)(cp + 4) = *(float4*)(&acc[i][4]);
        }
    } else {
        // scatter into q/k/v  [B,H,T,hd]
        int n = n0 + tx * 8;            // 8 consecutive cols, same region+head
        int region = n >> 10;
        int c = n & 1023;
        int h = c >> 6;
        int d = c & 63;
        float* buf = (region == 0) ? g_q : (region == 1) ? g_k : g_v;
        #pragma unroll
        for (int i = 0; i < 8; ++i) {
            int r  = m0 + ty * 8 + i;   // global row in [0, BT)
            int b  = r >> 11;           // / 2048
            int tt = r & 2047;
            float* dst = buf + ((((size_t)b * NHEAD + h) * SEQ + tt) * HDIM + d);
            *(float4*)(dst)     = *(float4*)(&acc[i][0]);
            *(float4*)(dst + 4) = *(float4*)(&acc[i][4]);
        }
    }
}

// ---------------------------------------------------------------------------
// Flash attention, fp32, causal. One query row per thread, BM=128 rows/block.
// KV tiles of 64 rows in smem; online softmax in chunks of 32 columns.
// Writes y in [B,T,C] layout for the projection GEMM.
// ---------------------------------------------------------------------------
__global__ __launch_bounds__(128) void flash_attn()
{
    __shared__ float Ks[64 * 64];
    __shared__ float Vs[64 * 64];

    int bh = blockIdx.y;                      // b*16 + h
    int qi = blockIdx.x * 128 + threadIdx.x;  // query row in [0, SEQ)

    const float* qp    = g_q + ((size_t)bh * SEQ + qi) * HDIM;
    const float* kbase = g_k + (size_t)bh * SEQ * HDIM;
    const float* vbase = g_v + (size_t)bh * SEQ * HDIM;

    float4 qr[16];
    #pragma unroll
    for (int w = 0; w < 16; ++w) qr[w] = *(const float4*)(qp + w * 4);

    float4 acc[16];
    #pragma unroll
    for (int w = 0; w < 16; ++w) acc[w] = make_float4(0.f, 0.f, 0.f, 0.f);

    float m = -1e30f, l = 0.f;
    const float scale = 0.125f;               // 1/sqrt(64)

    int ntiles = 2 * blockIdx.x + 2;          // covers all j <= qb+127

    for (int kt = 0; kt < ntiles; ++kt) {
        // cooperative load of 64x64 K and V tiles (4096 floats each)
        #pragma unroll
        for (int u = 0; u < 8; ++u) {
            int lin = threadIdx.x + u * 128;          // float4 index 0..1023
            ((float4*)Ks)[lin] = *(const float4*)(kbase + (size_t)kt * 64 * 64 + lin * 4);
            ((float4*)Vs)[lin] = *(const float4*)(vbase + (size_t)kt * 64 * 64 + lin * 4);
        }
        __syncthreads();

        int jbase = kt * 64;
        #pragma unroll
        for (int cch = 0; cch < 2; ++cch) {           // two chunks of 32 cols
            float s[32];
            #pragma unroll
            for (int j = 0; j < 32; ++j) {
                const float4* kr = (const float4*)(Ks + (cch * 32 + j) * 64);
                float dot = 0.f;
                #pragma unroll
                for (int w = 0; w < 16; ++w) {
                    float4 kv = kr[w];
                    dot += qr[w].x * kv.x + qr[w].y * kv.y
                         + qr[w].z * kv.z + qr[w].w * kv.w;
                }
                int jg = jbase + cch * 32 + j;
                s[j] = (jg <= qi) ? dot * scale : -1e30f;
            }
            float mt = -1e30f;
            #pragma unroll
            for (int j = 0; j < 32; ++j) mt = fmaxf(mt, s[j]);
            float mnew  = fmaxf(m, mt);
            float alpha = __expf(m - mnew);
            m = mnew;
            l *= alpha;
            #pragma unroll
            for (int w = 0; w < 16; ++w) {
                acc[w].x *= alpha; acc[w].y *= alpha;
                acc[w].z *= alpha; acc[w].w *= alpha;
            }
            #pragma unroll
            for (int j = 0; j < 32; ++j) {
                float p = __expf(s[j] - mnew);
                l += p;
                const float4* vr = (const float4*)(Vs + (cch * 32 + j) * 64);
                #pragma unroll
                for (int w = 0; w < 16; ++w) {
                    float4 vv = vr[w];
                    acc[w].x += p * vv.x; acc[w].y += p * vv.y;
                    acc[w].z += p * vv.z; acc[w].w += p * vv.w;
                }
            }
        }
        __syncthreads();
    }

    float inv = 1.f / l;
    int b = bh >> 4;
    int h = bh & 15;
    float* yp = g_y + ((size_t)(b * SEQ + qi)) * CDIM + h * HDIM;
    #pragma unroll
    for (int w = 0; w < 16; ++w) {
        float4 o = acc[w];
        o.x *= inv; o.y *= inv; o.z *= inv; o.w *= inv;
        *(float4*)(yp + w * 4) = o;
    }
}

// ---------------------------------------------------------------------------
// Launch: QKV GEMM -> flash attention -> proj GEMM
// ---------------------------------------------------------------------------
extern "C" void kernel_launch(void* const* d_in, const int* in_sizes, int n_in,
                              void* d_out, int out_size)
{
    const float* x      = (const float*)d_in[0];   // [4,2048,1024]
    const float* w_attn = (const float*)d_in[1];   // [1024,3072]
    const float* w_proj = (const float*)d_in[2];   // [1024,1024]
    float* out = (float*)d_out;                    // [4,2048,1024]

    float* yptr;
    cudaGetSymbolAddress((void**)&yptr, g_y);

    // 1) QKV: [8192,1024] @ [1024,3072] -> scatter to g_q/g_k/g_v
    {
        dim3 grid(QKV_N / 128, BT / 128);   // 24 x 64
        gemm128<1><<<grid, 256>>>(x, w_attn, nullptr, QKV_N, CDIM, CDIM, QKV_N);
    }
    // 2) attention
    {
        dim3 grid(SEQ / 128, BATCH * NHEAD);  // 16 x 64
        flash_attn<<<grid, 128>>>();
    }
    // 3) proj: [8192,1024] @ [1024,1024] -> out
    {
        dim3 grid(CDIM / 128, BT / 128);    // 8 x 64
        gemm128<0><<<grid, 256>>>(yptr, w_proj, out, CDIM, CDIM, CDIM, CDIM);
    }
}

// round 2
// speedup vs baseline: 2.1931x; 2.1931x over previous
#include <cuda_runtime.h>
#include <cuda_bf16.h>
#include <cstddef>
#include <cstdint>

// Problem constants
#define BATCH 4
#define SEQ   2048
#define CDIM  1024
#define NHEAD 16
#define HDIM  64
#define BT    (BATCH*SEQ)       // 8192
#define QKV_N (3*CDIM)          // 3072

// Scratch (device globals; no allocation allowed)
__device__ float g_q[BATCH*NHEAD*SEQ*HDIM];   // [B,H,T,hd]
__device__ float g_k[BATCH*NHEAD*SEQ*HDIM];
__device__ float g_v[BATCH*NHEAD*SEQ*HDIM];
__device__ float g_y[BT*CDIM];                // [B,T,C]

// ---------------------------------------------------------------------------
// Tiled fp32 GEMM (unchanged from round 1)
// ---------------------------------------------------------------------------
template<int EPI>
__global__ __launch_bounds__(256) void gemm128(
    const float* __restrict__ A, const float* __restrict__ B,
    float* __restrict__ C, int N, int K, int lda, int ldb)
{
    const int BK = 16;
    __shared__ float As[BK][132];
    __shared__ float Bs[BK][128];

    int t  = threadIdx.x;
    int tx = t & 15;
    int ty = t >> 4;
    int m0 = blockIdx.y * 128;
    int n0 = blockIdx.x * 128;

    float acc[8][8];
    #pragma unroll
    for (int i = 0; i < 8; ++i)
        #pragma unroll
        for (int j = 0; j < 8; ++j) acc[i][j] = 0.f;

    int ar = t >> 2;
    int ac = (t & 3) * 4;
    int br = t >> 5;
    int bc = (t & 31) * 4;

    for (int k0 = 0; k0 < K; k0 += BK) {
        #pragma unroll
        for (int rr = 0; rr < 2; ++rr) {
            int r = ar + rr * 64;
            float4 va = *(const float4*)(A + (size_t)(m0 + r) * lda + k0 + ac);
            As[ac + 0][r] = va.x;
            As[ac + 1][r] = va.y;
            As[ac + 2][r] = va.z;
            As[ac + 3][r] = va.w;
        }
        #pragma unroll
        for (int rr = 0; rr < 2; ++rr) {
            int r = br + rr * 8;
            *(float4*)(&Bs[r][bc]) =
                *(const float4*)(B + (size_t)(k0 + r) * ldb + n0 + bc);
        }
        __syncthreads();

        #pragma unroll
        for (int kk = 0; kk < BK; ++kk) {
            float a[8], b[8];
            *(float4*)(a)     = *(const float4*)(&As[kk][ty * 8]);
            *(float4*)(a + 4) = *(const float4*)(&As[kk][ty * 8 + 4]);
            *(float4*)(b)     = *(const float4*)(&Bs[kk][tx * 8]);
            *(float4*)(b + 4) = *(const float4*)(&Bs[kk][tx * 8 + 4]);
            #pragma unroll
            for (int i = 0; i < 8; ++i)
                #pragma unroll
                for (int j = 0; j < 8; ++j)
                    acc[i][j] += a[i] * b[j];
        }
        __syncthreads();
    }

    if (EPI == 0) {
        #pragma unroll
        for (int i = 0; i < 8; ++i) {
            float* cp = C + (size_t)(m0 + ty * 8 + i) * N + n0 + tx * 8;
            *(float4*)(cp)     = *(float4*)(&acc[i][0]);
            *(float4*)(cp + 4) = *(float4*)(&acc[i][4]);
        }
    } else {
        int n = n0 + tx * 8;
        int region = n >> 10;
        int c = n & 1023;
        int h = c >> 6;
        int d = c & 63;
        float* buf = (region == 0) ? g_q : (region == 1) ? g_k : g_v;
        #pragma unroll
        for (int i = 0; i < 8; ++i) {
            int r  = m0 + ty * 8 + i;
            int b  = r >> 11;
            int tt = r & 2047;
            float* dst = buf + ((((size_t)b * NHEAD + h) * SEQ + tt) * HDIM + d);
            *(float4*)(dst)     = *(float4*)(&acc[i][0]);
            *(float4*)(dst + 4) = *(float4*)(&acc[i][4]);
        }
    }
}

// ---------------------------------------------------------------------------
// Warp-MMA helpers (mma.sync m16n8k16 bf16, ldmatrix)
// ---------------------------------------------------------------------------
__device__ __forceinline__ uint32_t smem_u32(const void* p) {
    return (uint32_t)__cvta_generic_to_shared(p);
}

__device__ __forceinline__ void mma16816(float* c, const uint32_t* a,
                                         uint32_t b0, uint32_t b1) {
    asm volatile(
        "mma.sync.aligned.m16n8k16.row.col.f32.bf16.bf16.f32 "
        "{%0,%1,%2,%3},{%4,%5,%6,%7},{%8,%9},{%0,%1,%2,%3};"
        : "+f"(c[0]), "+f"(c[1]), "+f"(c[2]), "+f"(c[3])
        : "r"(a[0]), "r"(a[1]), "r"(a[2]), "r"(a[3]), "r"(b0), "r"(b1));
}

__device__ __forceinline__ void ldmx4(uint32_t* r, uint32_t addr) {
    asm volatile("ldmatrix.sync.aligned.m8n8.x4.shared.b16 {%0,%1,%2,%3},[%4];"
                 : "=r"(r[0]), "=r"(r[1]), "=r"(r[2]), "=r"(r[3]) : "r"(addr));
}
__device__ __forceinline__ void ldmx2(uint32_t& r0, uint32_t& r1, uint32_t addr) {
    asm volatile("ldmatrix.sync.aligned.m8n8.x2.shared.b16 {%0,%1},[%2];"
                 : "=r"(r0), "=r"(r1) : "r"(addr));
}
__device__ __forceinline__ void ldmx2t(uint32_t& r0, uint32_t& r1, uint32_t addr) {
    asm volatile("ldmatrix.sync.aligned.m8n8.x2.trans.shared.b16 {%0,%1},[%2];"
                 : "=r"(r0), "=r"(r1) : "r"(addr));
}

// split fp32 -> (hi, lo) bf16 pair stores (packed bf162)
__device__ __forceinline__ void split2(__nv_bfloat162* hp, __nv_bfloat162* lp,
                                       float x0, float x1) {
    __nv_bfloat16 h0 = __float2bfloat16(x0);
    __nv_bfloat16 h1 = __float2bfloat16(x1);
    *hp = __nv_bfloat162(h0, h1);
    *lp = __nv_bfloat162(__float2bfloat16(x0 - __bfloat162float(h0)),
                         __float2bfloat16(x1 - __bfloat162float(h1)));
}

// ---------------------------------------------------------------------------
// Flash attention with bf16-split tensor-core MMA.
// Block: 256 threads (8 warps), BM=128 queries, KV tile = 64 keys.
// Each warp owns 16 query rows. 3-term split: hi*hi + hi*lo + lo*hi.
// ---------------------------------------------------------------------------
#define LDK 72   // padded smem row (bf16 elems)

__global__ __launch_bounds__(256) void flash_attn_mma()
{
    __shared__ __nv_bfloat16 sm[4 * 64 * LDK];   // 36,864 B
    __nv_bfloat16* kh = sm;
    __nv_bfloat16* kl = sm + 64 * LDK;
    __nv_bfloat16* vh = sm + 2 * 64 * LDK;
    __nv_bfloat16* vl = sm + 3 * 64 * LDK;

    int t = threadIdx.x, lane = t & 31, w = t >> 5;
    int bx = blockIdx.x, bh = blockIdx.y;
    int b = bh >> 4, h = bh & 15;

    const float* qg = g_q + ((size_t)bh * SEQ + bx * 128) * HDIM;
    const float* kg = g_k + (size_t)bh * SEQ * HDIM;
    const float* vg = g_v + (size_t)bh * SEQ * HDIM;

    // ---- stage Q tile (128x64) as bf16 hi/lo, then build register fragments
    {
        __nv_bfloat16* qhi_s = sm;               // rows 0..127 in kh+kl space
        __nv_bfloat16* qlo_s = sm + 2 * 64 * LDK;
        #pragma unroll
        for (int i = 0; i < 8; ++i) {
            int idx = t + i * 256;               // float4 index, 2048 total
            int r = idx >> 4, c = (idx & 15) * 4;
            float4 v = *(const float4*)(qg + r * 64 + c);
            split2((__nv_bfloat162*)&qhi_s[r * LDK + c],
                   (__nv_bfloat162*)&qlo_s[r * LDK + c], v.x, v.y);
            split2((__nv_bfloat162*)&qhi_s[r * LDK + c + 2],
                   (__nv_bfloat162*)&qlo_s[r * LDK + c + 2], v.z, v.w);
        }
        __syncthreads();

        // fragments loaded below into qhf/qlf
    }

    uint32_t qhf[4][4], qlf[4][4];
    {
        __nv_bfloat16* qhi_s = sm;
        __nv_bfloat16* qlo_s = sm + 2 * 64 * LDK;
        int row = w * 16 + (lane & 15);
        #pragma unroll
        for (int kt = 0; kt < 4; ++kt) {
            int col = kt * 16 + (lane >> 4) * 8;
            ldmx4(qhf[kt], smem_u32(&qhi_s[row * LDK + col]));
            ldmx4(qlf[kt], smem_u32(&qlo_s[row * LDK + col]));
        }
    }
    __syncthreads();

    float oacc[8][4];
    #pragma unroll
    for (int i = 0; i < 8; ++i) { oacc[i][0]=0.f; oacc[i][1]=0.f; oacc[i][2]=0.f; oacc[i][3]=0.f; }

    float m0 = -1e30f, m1 = -1e30f, l0 = 0.f, l1 = 0.f;
    int g    = lane >> 2;
    int qoff = (lane & 3) * 2;
    int rw   = bx * 128 + w * 16;            // first query row of this warp
    const float scale = 0.125f;

    int ntiles = 2 * bx + 2;
    for (int kt = 0; kt < ntiles; ++kt) {
        // ---- cooperative load of K/V tile (64x64 fp32 each) -> bf16 hi/lo
        #pragma unroll
        for (int i = 0; i < 4; ++i) {
            int idx = t + i * 256;                 // float4 index, 1024 total
            int r = idx >> 4, c = (idx & 15) * 4;
            float4 kv = *(const float4*)(kg + (size_t)kt * 4096 + r * 64 + c);
            float4 vv = *(const float4*)(vg + (size_t)kt * 4096 + r * 64 + c);
            split2((__nv_bfloat162*)&kh[r * LDK + c],
                   (__nv_bfloat162*)&kl[r * LDK + c], kv.x, kv.y);
            split2((__nv_bfloat162*)&kh[r * LDK + c + 2],
                   (__nv_bfloat162*)&kl[r * LDK + c + 2], kv.z, kv.w);
            split2((__nv_bfloat162*)&vh[r * LDK + c],
                   (__nv_bfloat162*)&vl[r * LDK + c], vv.x, vv.y);
            split2((__nv_bfloat162*)&vh[r * LDK + c + 2],
                   (__nv_bfloat162*)&vl[r * LDK + c + 2], vv.z, vv.w);
        }
        __syncthreads();

        if (kt * 64 <= rw + 15) {           // warp has visible keys in this tile
            // ---- S = Q K^T (3-term split), per-warp 16x64
            float sacc[8][4];
            #pragma unroll
            for (int i = 0; i < 8; ++i) { sacc[i][0]=0.f; sacc[i][1]=0.f; sacc[i][2]=0.f; sacc[i][3]=0.f; }

            #pragma unroll
            for (int nt = 0; nt < 8; ++nt) {
                int keyr = nt * 8 + (lane & 7);
                #pragma unroll
                for (int c = 0; c < 4; ++c) {
                    int col = c * 16 + (((lane & 15) >> 3)) * 8;
                    uint32_t bh0, bh1, bl0, bl1;
                    ldmx2(bh0, bh1, smem_u32(&kh[keyr * LDK + col]));
                    ldmx2(bl0, bl1, smem_u32(&kl[keyr * LDK + col]));
                    mma16816(sacc[nt], qhf[c], bh0, bh1);
                    mma16816(sacc[nt], qhf[c], bl0, bl1);
                    mma16816(sacc[nt], qlf[c], bh0, bh1);
                }
            }

            // ---- scale + causal mask + row max
            int i0 = rw + g, i1 = rw + g + 8;
            float mt0 = -1e30f, mt1 = -1e30f;
            #pragma unroll
            for (int nt = 0; nt < 8; ++nt) {
                int j0 = kt * 64 + nt * 8 + qoff;
                float s0 = sacc[nt][0] * scale;
                float s1 = sacc[nt][1] * scale;
                float s2 = sacc[nt][2] * scale;
                float s3 = sacc[nt][3] * scale;
                if (j0     > i0) s0 = -1e30f;
                if (j0 + 1 > i0) s1 = -1e30f;
                if (j0     > i1) s2 = -1e30f;
                if (j0 + 1 > i1) s3 = -1e30f;
                sacc[nt][0] = s0; sacc[nt][1] = s1;
                sacc[nt][2] = s2; sacc[nt][3] = s3;
                mt0 = fmaxf(mt0, fmaxf(s0, s1));
                mt1 = fmaxf(mt1, fmaxf(s2, s3));
            }
            mt0 = fmaxf(mt0, __shfl_xor_sync(0xffffffffu, mt0, 1));
            mt0 = fmaxf(mt0, __shfl_xor_sync(0xffffffffu, mt0, 2));
            mt1 = fmaxf(mt1, __shfl_xor_sync(0xffffffffu, mt1, 1));
            mt1 = fmaxf(mt1, __shfl_xor_sync(0xffffffffu, mt1, 2));

            float mn0 = fmaxf(m0, mt0), mn1 = fmaxf(m1, mt1);
            float a0 = __expf(m0 - mn0), a1 = __expf(m1 - mn1);
            m0 = mn0; m1 = mn1;
            l0 *= a0;  l1 *= a1;
            #pragma unroll
            for (int nt = 0; nt < 8; ++nt) {
                oacc[nt][0] *= a0; oacc[nt][1] *= a0;
                oacc[nt][2] *= a1; oacc[nt][3] *= a1;
            }

            // ---- P = exp(S - m), convert to split a-fragments, O += P V
            #pragma unroll
            for (int c2 = 0; c2 < 4; ++c2) {
                float p0 = __expf(sacc[2*c2  ][0] - m0);
                float p1 = __expf(sacc[2*c2  ][1] - m0);
                float p2 = __expf(sacc[2*c2  ][2] - m1);
                float p3 = __expf(sacc[2*c2  ][3] - m1);
                float p4 = __expf(sacc[2*c2+1][0] - m0);
                float p5 = __expf(sacc[2*c2+1][1] - m0);
                float p6 = __expf(sacc[2*c2+1][2] - m1);
                float p7 = __expf(sacc[2*c2+1][3] - m1);
                l0 += p0 + p1 + p4 + p5;
                l1 += p2 + p3 + p6 + p7;

                uint32_t ph[4], pl[4];
                {
                    __nv_bfloat162 hp, lp;
                    split2(&hp, &lp, p0, p1); ph[0] = *(uint32_t*)&hp; pl[0] = *(uint32_t*)&lp;
                    split2(&hp, &lp, p2, p3); ph[1] = *(uint32_t*)&hp; pl[1] = *(uint32_t*)&lp;
                    split2(&hp, &lp, p4, p5); ph[2] = *(uint32_t*)&hp; pl[2] = *(uint32_t*)&lp;
                    split2(&hp, &lp, p6, p7); ph[3] = *(uint32_t*)&hp; pl[3] = *(uint32_t*)&lp;
                }

                int keyr = c2 * 16 + (lane & 15);
                #pragma unroll
                for (int nt = 0; nt < 8; ++nt) {
                    uint32_t bv0, bv1, bw0, bw1;
                    ldmx2t(bv0, bv1, smem_u32(&vh[keyr * LDK + nt * 8]));
                    ldmx2t(bw0, bw1, smem_u32(&vl[keyr * LDK + nt * 8]));
                    mma16816(oacc[nt], ph, bv0, bv1);
                    mma16816(oacc[nt], ph, bw0, bw1);
                    mma16816(oacc[nt], pl, bv0, bv1);
                }
            }
        }
        __syncthreads();
    }

    // ---- finalize: reduce l across the quad, normalize, write [B,T,C]
    l0 += __shfl_xor_sync(0xffffffffu, l0, 1);
    l0 += __shfl_xor_sync(0xffffffffu, l0, 2);
    l1 += __shfl_xor_sync(0xffffffffu, l1, 1);
    l1 += __shfl_xor_sync(0xffffffffu, l1, 2);
    float inv0 = 1.f / l0, inv1 = 1.f / l1;

    float* yp0 = g_y + ((size_t)(b * SEQ + rw + g    )) * CDIM + h * 64;
    float* yp1 = g_y + ((size_t)(b * SEQ + rw + g + 8)) * CDIM + h * 64;
    #pragma unroll
    for (int nt = 0; nt < 8; ++nt) {
        float2 o0 = make_float2(oacc[nt][0] * inv0, oacc[nt][1] * inv0);
        float2 o1 = make_float2(oacc[nt][2] * inv1, oacc[nt][3] * inv1);
        *(float2*)(yp0 + nt * 8 + qoff) = o0;
        *(float2*)(yp1 + nt * 8 + qoff) = o1;
    }
}

// ---------------------------------------------------------------------------
// Launch: QKV GEMM -> flash attention (tensor core) -> proj GEMM
// ---------------------------------------------------------------------------
extern "C" void kernel_launch(void* const* d_in, const int* in_sizes, int n_in,
                              void* d_out, int out_size)
{
    const float* x      = (const float*)d_in[0];   // [4,2048,1024]
    const float* w_attn = (const float*)d_in[1];   // [1024,3072]
    const float* w_proj = (const float*)d_in[2];   // [1024,1024]
    float* out = (float*)d_out;                    // [4,2048,1024]

    float* yptr;
    cudaGetSymbolAddress((void**)&yptr, g_y);

    // 1) QKV: [8192,1024] @ [1024,3072] -> scatter to g_q/g_k/g_v
    {
        dim3 grid(QKV_N / 128, BT / 128);   // 24 x 64
        gemm128<1><<<grid, 256>>>(x, w_attn, nullptr, QKV_N, CDIM, CDIM, QKV_N);
    }
    // 2) attention (warp-MMA bf16-split flash)
    {
        dim3 grid(SEQ / 128, BATCH * NHEAD);  // 16 x 64
        flash_attn_mma<<<grid, 256>>>();
    }
    // 3) proj: [8192,1024] @ [1024,1024] -> out
    {
        dim3 grid(CDIM / 128, BT / 128);    // 8 x 64
        gemm128<0><<<grid, 256>>>(yptr, w_proj, out, CDIM, CDIM, CDIM, CDIM);
    }
}

// round 3
// speedup vs baseline: 4.2737x; 1.9487x over previous
#include <cuda_runtime.h>
#include <cuda_bf16.h>
#include <cstddef>
#include <cstdint>

// Problem constants
#define BATCH 4
#define SEQ   2048
#define CDIM  1024
#define NHEAD 16
#define HDIM  64
#define BT    (BATCH*SEQ)       // 8192
#define QKV_N (3*CDIM)          // 3072

// Scratch (device globals; no allocation allowed)
__device__ float g_q[BATCH*NHEAD*SEQ*HDIM];   // [B,H,T,hd] fp32
__device__ float g_k[BATCH*NHEAD*SEQ*HDIM];
__device__ float g_v[BATCH*NHEAD*SEQ*HDIM];
__device__ __nv_bfloat16 g_xh[BT*CDIM], g_xl[BT*CDIM];        // split x
__device__ __nv_bfloat16 g_yh[BT*CDIM], g_yl[BT*CDIM];        // split attention out [B,T,C]
__device__ __nv_bfloat16 g_wah[CDIM*QKV_N], g_wal[CDIM*QKV_N];
__device__ __nv_bfloat16 g_wph[CDIM*CDIM],  g_wpl[CDIM*CDIM];

// ---------------------------------------------------------------------------
// MMA / ldmatrix / cp.async helpers
// ---------------------------------------------------------------------------
__device__ __forceinline__ uint32_t smem_u32(const void* p) {
    return (uint32_t)__cvta_generic_to_shared(p);
}
__device__ __forceinline__ void mma16816(float* c, const uint32_t* a,
                                         uint32_t b0, uint32_t b1) {
    asm volatile(
        "mma.sync.aligned.m16n8k16.row.col.f32.bf16.bf16.f32 "
        "{%0,%1,%2,%3},{%4,%5,%6,%7},{%8,%9},{%0,%1,%2,%3};"
        : "+f"(c[0]), "+f"(c[1]), "+f"(c[2]), "+f"(c[3])
        : "r"(a[0]), "r"(a[1]), "r"(a[2]), "r"(a[3]), "r"(b0), "r"(b1));
}
__device__ __forceinline__ void ldmx4(uint32_t* r, uint32_t addr) {
    asm volatile("ldmatrix.sync.aligned.m8n8.x4.shared.b16 {%0,%1,%2,%3},[%4];"
                 : "=r"(r[0]), "=r"(r[1]), "=r"(r[2]), "=r"(r[3]) : "r"(addr));
}
__device__ __forceinline__ void ldmx2(uint32_t& r0, uint32_t& r1, uint32_t addr) {
    asm volatile("ldmatrix.sync.aligned.m8n8.x2.shared.b16 {%0,%1},[%2];"
                 : "=r"(r0), "=r"(r1) : "r"(addr));
}
__device__ __forceinline__ void ldmx2t(uint32_t& r0, uint32_t& r1, uint32_t addr) {
    asm volatile("ldmatrix.sync.aligned.m8n8.x2.trans.shared.b16 {%0,%1},[%2];"
                 : "=r"(r0), "=r"(r1) : "r"(addr));
}
__device__ __forceinline__ void cp16(uint32_t saddr, const void* g) {
    asm volatile("cp.async.cg.shared.global [%0], [%1], 16;" :: "r"(saddr), "l"(g));
}
__device__ __forceinline__ void cp_commit() { asm volatile("cp.async.commit_group;"); }
template<int Np> __device__ __forceinline__ void cp_wait() {
    asm volatile("cp.async.wait_group %0;" :: "n"(Np));
}

// split fp32 -> (hi, lo) bf16 pair (packed bf162)
__device__ __forceinline__ void split2(__nv_bfloat162* hp, __nv_bfloat162* lp,
                                       float x0, float x1) {
    __nv_bfloat16 h0 = __float2bfloat16(x0);
    __nv_bfloat16 h1 = __float2bfloat16(x1);
    *hp = __nv_bfloat162(h0, h1);
    *lp = __nv_bfloat162(__float2bfloat16(x0 - __bfloat162float(h0)),
                         __float2bfloat16(x1 - __bfloat162float(h1)));
}

// ---------------------------------------------------------------------------
// Prep: split fp32 array into bf16 hi/lo
// ---------------------------------------------------------------------------
__global__ __launch_bounds__(256) void split_fp32(
    const float4* __restrict__ in, __nv_bfloat162* __restrict__ h,
    __nv_bfloat162* __restrict__ l, int n4)
{
    int i = blockIdx.x * 256 + threadIdx.x;
    if (i >= n4) return;
    float4 v = in[i];
    __nv_bfloat162 h0, l0, h1, l1;
    split2(&h0, &l0, v.x, v.y);
    split2(&h1, &l1, v.z, v.w);
    h[i * 2] = h0; h[i * 2 + 1] = h1;
    l[i * 2] = l0; l[i * 2 + 1] = l1;
}

// ---------------------------------------------------------------------------
// bf16-split tensor-core GEMM: C[M,N] = A[M,K] @ B[K,N], fp32-accurate.
// 128x128 block tile, BK=32, 8 warps (2x4 -> warp tile 64x32).
// cp.async double-buffered, XOR-swizzled smem (conflict-free ldmatrix).
// EPI=0: plain row-major C. EPI=1: QKV scatter to g_q/g_k/g_v.
// ---------------------------------------------------------------------------
#define STAGE_BYTES 32768   // Ah(8K) Al(8K) Bh(8K) Bl(8K)

template<int EPI>
__global__ __launch_bounds__(256)
void gemm_bf16split(const __nv_bfloat16* __restrict__ Ah,
                    const __nv_bfloat16* __restrict__ Al,
                    const __nv_bfloat16* __restrict__ Bh,
                    const __nv_bfloat16* __restrict__ Bl,
                    float* __restrict__ C, int N, int K)
{
    extern __shared__ char smem[];
    const uint32_t sbase = smem_u32(smem);

    const int t = threadIdx.x, lane = t & 31, w = t >> 5;
    const int m0 = blockIdx.y * 128, n0 = blockIdx.x * 128;
    const int wm = w & 1, wn = w >> 1;

    float acc[4][4][4] = {};

    const int NIT = K / 32;

    auto load_stage = [&](int it, int buf) {
        uint32_t sb = sbase + buf * STAGE_BYTES;
        int k0 = it * 32;
        // A tiles (128x32): 512 16B-chunks per hi/lo; 2 per thread
        #pragma unroll
        for (int u = 0; u < 2; ++u) {
            int q = t + u * 256;
            int r = q >> 2, c16 = q & 3;
            uint32_t sc = (uint32_t)(r * 4 + (c16 ^ ((r >> 1) & 3))) * 16;
            size_t go = (size_t)(m0 + r) * K + k0 + c16 * 8;
            cp16(sb + sc,        Ah + go);
            cp16(sb + 8192 + sc, Al + go);
        }
        // B tiles (32x128): 512 chunks per hi/lo; 2 per thread
        #pragma unroll
        for (int u = 0; u < 2; ++u) {
            int q = t + u * 256;
            int k = q >> 4, c16 = q & 15;
            uint32_t sc = (uint32_t)(k * 16 + (c16 ^ (k & 7))) * 16;
            size_t go = (size_t)(k0 + k) * N + n0 + c16 * 8;
            cp16(sb + 16384 + sc, Bh + go);
            cp16(sb + 24576 + sc, Bl + go);
        }
    };

    load_stage(0, 0);
    cp_commit();

    for (int it = 0; it < NIT; ++it) {
        if (it + 1 < NIT) {
            load_stage(it + 1, (it + 1) & 1);
            cp_commit();
            cp_wait<1>();
        } else {
            cp_wait<0>();
        }
        __syncthreads();

        uint32_t sb  = sbase + (it & 1) * STAGE_BYTES;
        uint32_t sAh = sb, sAl = sb + 8192, sBh = sb + 16384, sBl = sb + 24576;

        #pragma unroll
        for (int kk = 0; kk < 2; ++kk) {
            uint32_t ah[4][4], al[4][4], bh[4][2], bl[4][2];
            #pragma unroll
            for (int mt = 0; mt < 4; ++mt) {
                int r = wm * 64 + mt * 16 + (lane & 15);
                int c16 = kk * 2 + (lane >> 4);
                uint32_t off = (uint32_t)(r * 4 + (c16 ^ ((r >> 1) & 3))) * 16;
                ldmx4(ah[mt], sAh + off);
                ldmx4(al[mt], sAl + off);
            }
            #pragma unroll
            for (int nt = 0; nt < 4; ++nt) {
                int k = kk * 16 + (lane & 15);
                int c16 = wn * 4 + nt;
                uint32_t off = (uint32_t)(k * 16 + (c16 ^ (k & 7))) * 16;
                ldmx2t(bh[nt][0], bh[nt][1], sBh + off);
                ldmx2t(bl[nt][0], bl[nt][1], sBl + off);
            }
            #pragma unroll
            for (int mt = 0; mt < 4; ++mt)
                #pragma unroll
                for (int nt = 0; nt < 4; ++nt) {
                    mma16816(acc[mt][nt], ah[mt], bh[nt][0], bh[nt][1]);
                    mma16816(acc[mt][nt], ah[mt], bl[nt][0], bl[nt][1]);
                    mma16816(acc[mt][nt], al[mt], bh[nt][0], bh[nt][1]);
                }
        }
        __syncthreads();
    }

    // epilogue
    int g = lane >> 2, qoff = (lane & 3) * 2;
    if (EPI == 0) {
        #pragma unroll
        for (int mt = 0; mt < 4; ++mt) {
            int r0 = m0 + wm * 64 + mt * 16 + g;
            #pragma unroll
            for (int nt = 0; nt < 4; ++nt) {
                int n = n0 + wn * 32 + nt * 8 + qoff;
                *(float2*)(C + (size_t)r0 * N + n) =
                    make_float2(acc[mt][nt][0], acc[mt][nt][1]);
                *(float2*)(C + (size_t)(r0 + 8) * N + n) =
                    make_float2(acc[mt][nt][2], acc[mt][nt][3]);
            }
        }
    } else {
        #pragma unroll
        for (int mt = 0; mt < 4; ++mt) {
            int r = m0 + wm * 64 + mt * 16 + g;
            int b = r >> 11, tt = r & 2047;
            #pragma unroll
            for (int nt = 0; nt < 4; ++nt) {
                int n = n0 + wn * 32 + nt * 8 + qoff;
                int region = n >> 10, c = n & 1023, h = c >> 6, d = c & 63;
                float* buf = (region == 0) ? g_q : (region == 1) ? g_k : g_v;
                float* dst = buf + ((((size_t)b * NHEAD + h) * SEQ + tt) * HDIM + d);
                *(float2*)dst = make_float2(acc[mt][nt][0], acc[mt][nt][1]);
                *(float2*)(dst + 8 * HDIM) = make_float2(acc[mt][nt][2], acc[mt][nt][3]);
            }
        }
    }
}

// ---------------------------------------------------------------------------
// Flash attention with bf16-split tensor-core MMA (validated round 2).
// Epilogue now writes y split directly into g_yh/g_yl.
// ---------------------------------------------------------------------------
#define LDK 72   // padded smem row (bf16 elems)

__global__ __launch_bounds__(256) void flash_attn_mma()
{
    __shared__ __nv_bfloat16 sm[4 * 64 * LDK];
    __nv_bfloat16* kh = sm;
    __nv_bfloat16* kl = sm + 64 * LDK;
    __nv_bfloat16* vh = sm + 2 * 64 * LDK;
    __nv_bfloat16* vl = sm + 3 * 64 * LDK;

    int t = threadIdx.x, lane = t & 31, w = t >> 5;
    int bx = blockIdx.x, bh2 = blockIdx.y;
    int b = bh2 >> 4, h = bh2 & 15;

    const float* qg = g_q + ((size_t)bh2 * SEQ + bx * 128) * HDIM;
    const float* kg = g_k + (size_t)bh2 * SEQ * HDIM;
    const float* vg = g_v + (size_t)bh2 * SEQ * HDIM;

    // stage Q tile (128x64) as bf16 hi/lo
    {
        __nv_bfloat16* qhi_s = sm;
        __nv_bfloat16* qlo_s = sm + 2 * 64 * LDK;
        #pragma unroll
        for (int i = 0; i < 8; ++i) {
            int idx = t + i * 256;
            int r = idx >> 4, c = (idx & 15) * 4;
            float4 v = *(const float4*)(qg + r * 64 + c);
            split2((__nv_bfloat162*)&qhi_s[r * LDK + c],
                   (__nv_bfloat162*)&qlo_s[r * LDK + c], v.x, v.y);
            split2((__nv_bfloat162*)&qhi_s[r * LDK + c + 2],
                   (__nv_bfloat162*)&qlo_s[r * LDK + c + 2], v.z, v.w);
        }
        __syncthreads();
    }

    uint32_t qhf[4][4], qlf[4][4];
    {
        __nv_bfloat16* qhi_s = sm;
        __nv_bfloat16* qlo_s = sm + 2 * 64 * LDK;
        int row = w * 16 + (lane & 15);
        #pragma unroll
        for (int kt = 0; kt < 4; ++kt) {
            int col = kt * 16 + (lane >> 4) * 8;
            ldmx4(qhf[kt], smem_u32(&qhi_s[row * LDK + col]));
            ldmx4(qlf[kt], smem_u32(&qlo_s[row * LDK + col]));
        }
    }
    __syncthreads();

    float oacc[8][4];
    #pragma unroll
    for (int i = 0; i < 8; ++i) { oacc[i][0]=0.f; oacc[i][1]=0.f; oacc[i][2]=0.f; oacc[i][3]=0.f; }

    float m0 = -1e30f, m1 = -1e30f, l0 = 0.f, l1 = 0.f;
    int g    = lane >> 2;
    int qoff = (lane & 3) * 2;
    int rw   = bx * 128 + w * 16;
    const float scale = 0.125f;

    int ntiles = 2 * bx + 2;
    for (int kt = 0; kt < ntiles; ++kt) {
        #pragma unroll
        for (int i = 0; i < 4; ++i) {
            int idx = t + i * 256;
            int r = idx >> 4, c = (idx & 15) * 4;
            float4 kv = *(const float4*)(kg + (size_t)kt * 4096 + r * 64 + c);
            float4 vv = *(const float4*)(vg + (size_t)kt * 4096 + r * 64 + c);
            split2((__nv_bfloat162*)&kh[r * LDK + c],
                   (__nv_bfloat162*)&kl[r * LDK + c], kv.x, kv.y);
            split2((__nv_bfloat162*)&kh[r * LDK + c + 2],
                   (__nv_bfloat162*)&kl[r * LDK + c + 2], kv.z, kv.w);
            split2((__nv_bfloat162*)&vh[r * LDK + c],
                   (__nv_bfloat162*)&vl[r * LDK + c], vv.x, vv.y);
            split2((__nv_bfloat162*)&vh[r * LDK + c + 2],
                   (__nv_bfloat162*)&vl[r * LDK + c + 2], vv.z, vv.w);
        }
        __syncthreads();

        if (kt * 64 <= rw + 15) {
            float sacc[8][4];
            #pragma unroll
            for (int i = 0; i < 8; ++i) { sacc[i][0]=0.f; sacc[i][1]=0.f; sacc[i][2]=0.f; sacc[i][3]=0.f; }

            #pragma unroll
            for (int nt = 0; nt < 8; ++nt) {
                int keyr = nt * 8 + (lane & 7);
                #pragma unroll
                for (int c = 0; c < 4; ++c) {
                    int col = c * 16 + (((lane & 15) >> 3)) * 8;
                    uint32_t bh0, bh1, bl0, bl1;
                    ldmx2(bh0, bh1, smem_u32(&kh[keyr * LDK + col]));
                    ldmx2(bl0, bl1, smem_u32(&kl[keyr * LDK + col]));
                    mma16816(sacc[nt], qhf[c], bh0, bh1);
                    mma16816(sacc[nt], qhf[c], bl0, bl1);
                    mma16816(sacc[nt], qlf[c], bh0, bh1);
                }
            }

            int i0 = rw + g, i1 = rw + g + 8;
            float mt0 = -1e30f, mt1 = -1e30f;
            #pragma unroll
            for (int nt = 0; nt < 8; ++nt) {
                int j0 = kt * 64 + nt * 8 + qoff;
                float s0 = sacc[nt][0] * scale;
                float s1 = sacc[nt][1] * scale;
                float s2 = sacc[nt][2] * scale;
                float s3 = sacc[nt][3] * scale;
                if (j0     > i0) s0 = -1e30f;
                if (j0 + 1 > i0) s1 = -1e30f;
                if (j0     > i1) s2 = -1e30f;
                if (j0 + 1 > i1) s3 = -1e30f;
                sacc[nt][0] = s0; sacc[nt][1] = s1;
                sacc[nt][2] = s2; sacc[nt][3] = s3;
                mt0 = fmaxf(mt0, fmaxf(s0, s1));
                mt1 = fmaxf(mt1, fmaxf(s2, s3));
            }
            mt0 = fmaxf(mt0, __shfl_xor_sync(0xffffffffu, mt0, 1));
            mt0 = fmaxf(mt0, __shfl_xor_sync(0xffffffffu, mt0, 2));
            mt1 = fmaxf(mt1, __shfl_xor_sync(0xffffffffu, mt1, 1));
            mt1 = fmaxf(mt1, __shfl_xor_sync(0xffffffffu, mt1, 2));

            float mn0 = fmaxf(m0, mt0), mn1 = fmaxf(m1, mt1);
            float a0 = __expf(m0 - mn0), a1 = __expf(m1 - mn1);
            m0 = mn0; m1 = mn1;
            l0 *= a0;  l1 *= a1;
            #pragma unroll
            for (int nt = 0; nt < 8; ++nt) {
                oacc[nt][0] *= a0; oacc[nt][1] *= a0;
                oacc[nt][2] *= a1; oacc[nt][3] *= a1;
            }

            #pragma unroll
            for (int c2 = 0; c2 < 4; ++c2) {
                float p0 = __expf(sacc[2*c2  ][0] - m0);
                float p1 = __expf(sacc[2*c2  ][1] - m0);
                float p2 = __expf(sacc[2*c2  ][2] - m1);
                float p3 = __expf(sacc[2*c2  ][3] - m1);
                float p4 = __expf(sacc[2*c2+1][0] - m0);
                float p5 = __expf(sacc[2*c2+1][1] - m0);
                float p6 = __expf(sacc[2*c2+1][2] - m1);
                float p7 = __expf(sacc[2*c2+1][3] - m1);
                l0 += p0 + p1 + p4 + p5;
                l1 += p2 + p3 + p6 + p7;

                uint32_t ph[4], pl[4];
                {
                    __nv_bfloat162 hp, lp;
                    split2(&hp, &lp, p0, p1); ph[0] = *(uint32_t*)&hp; pl[0] = *(uint32_t*)&lp;
                    split2(&hp, &lp, p2, p3); ph[1] = *(uint32_t*)&hp; pl[1] = *(uint32_t*)&lp;
                    split2(&hp, &lp, p4, p5); ph[2] = *(uint32_t*)&hp; pl[2] = *(uint32_t*)&lp;
                    split2(&hp, &lp, p6, p7); ph[3] = *(uint32_t*)&hp; pl[3] = *(uint32_t*)&lp;
                }

                int keyr = c2 * 16 + (lane & 15);
                #pragma unroll
                for (int nt = 0; nt < 8; ++nt) {
                    uint32_t bv0, bv1, bw0, bw1;
                    ldmx2t(bv0, bv1, smem_u32(&vh[keyr * LDK + nt * 8]));
                    ldmx2t(bw0, bw1, smem_u32(&vl[keyr * LDK + nt * 8]));
                    mma16816(oacc[nt], ph, bv0, bv1);
                    mma16816(oacc[nt], ph, bw0, bw1);
                    mma16816(oacc[nt], pl, bv0, bv1);
                }
            }
        }
        __syncthreads();
    }

    l0 += __shfl_xor_sync(0xffffffffu, l0, 1);
    l0 += __shfl_xor_sync(0xffffffffu, l0, 2);
    l1 += __shfl_xor_sync(0xffffffffu, l1, 1);
    l1 += __shfl_xor_sync(0xffffffffu, l1, 2);
    float inv0 = 1.f / l0, inv1 = 1.f / l1;

    size_t o0 = ((size_t)(b * SEQ + rw + g    )) * CDIM + h * 64;
    size_t o1 = ((size_t)(b * SEQ + rw + g + 8)) * CDIM + h * 64;
    #pragma unroll
    for (int nt = 0; nt < 8; ++nt) {
        __nv_bfloat162 hp, lp;
        split2(&hp, &lp, oacc[nt][0] * inv0, oacc[nt][1] * inv0);
        *(__nv_bfloat162*)(g_yh + o0 + nt * 8 + qoff) = hp;
        *(__nv_bfloat162*)(g_yl + o0 + nt * 8 + qoff) = lp;
        split2(&hp, &lp, oacc[nt][2] * inv1, oacc[nt][3] * inv1);
        *(__nv_bfloat162*)(g_yh + o1 + nt * 8 + qoff) = hp;
        *(__nv_bfloat162*)(g_yl + o1 + nt * 8 + qoff) = lp;
    }
}

// ---------------------------------------------------------------------------
// Launch: split -> QKV GEMM -> attention -> proj GEMM
// ---------------------------------------------------------------------------
extern "C" void kernel_launch(void* const* d_in, const int* in_sizes, int n_in,
                              void* d_out, int out_size)
{
    const float* x      = (const float*)d_in[0];
    const float* w_attn = (const float*)d_in[1];
    const float* w_proj = (const float*)d_in[2];
    float* out = (float*)d_out;

    __nv_bfloat16 *xh, *xl, *yh, *yl, *wah, *wal, *wph, *wpl;
    cudaGetSymbolAddress((void**)&xh,  g_xh);  cudaGetSymbolAddress((void**)&xl,  g_xl);
    cudaGetSymbolAddress((void**)&yh,  g_yh);  cudaGetSymbolAddress((void**)&yl,  g_yl);
    cudaGetSymbolAddress((void**)&wah, g_wah); cudaGetSymbolAddress((void**)&wal, g_wal);
    cudaGetSymbolAddress((void**)&wph, g_wph); cudaGetSymbolAddress((void**)&wpl, g_wpl);

    cudaFuncSetAttribute(gemm_bf16split<0>,
                         cudaFuncAttributeMaxDynamicSharedMemorySize, 2 * STAGE_BYTES);
    cudaFuncSetAttribute(gemm_bf16split<1>,
                         cudaFuncAttributeMaxDynamicSharedMemorySize, 2 * STAGE_BYTES);

    // splits
    split_fp32<<<(BT * CDIM / 4) / 256, 256>>>(
        (const float4*)x, (__nv_bfloat162*)xh, (__nv_bfloat162*)xl, BT * CDIM / 4);
    split_fp32<<<(CDIM * QKV_N / 4) / 256, 256>>>(
        (const float4*)w_attn, (__nv_bfloat162*)wah, (__nv_bfloat162*)wal, CDIM * QKV_N / 4);
    split_fp32<<<(CDIM * CDIM / 4) / 256, 256>>>(
        (const float4*)w_proj, (__nv_bfloat162*)wph, (__nv_bfloat162*)wpl, CDIM * CDIM / 4);

    // 1) QKV GEMM: [8192,1024]@[1024,3072] -> scatter q/k/v
    {
        dim3 grid(QKV_N / 128, BT / 128);
        gemm_bf16split<1><<<grid, 256, 2 * STAGE_BYTES>>>(xh, xl, wah, wal,
                                                          nullptr, QKV_N, CDIM);
    }
    // 2) attention
    {
        dim3 grid(SEQ / 128, BATCH * NHEAD);
        flash_attn_mma<<<grid, 256>>>();
    }
    // 3) proj GEMM: [8192,1024]@[1024,1024] -> out
    {
        dim3 grid(CDIM / 128, BT / 128);
        gemm_bf16split<0><<<grid, 256, 2 * STAGE_BYTES>>>(yh, yl, wph, wpl,
                                                          out, CDIM, CDIM);
    }
}

// round 5
// speedup vs baseline: 4.5183x; 1.0572x over previous
#include <cuda_runtime.h>
#include <cuda_bf16.h>
#include <cstddef>
#include <cstdint>

// Problem constants
#define BATCH 4
#define SEQ   2048
#define CDIM  1024
#define NHEAD 16
#define HDIM  64
#define BT    (BATCH*SEQ)       // 8192
#define QKV_N (3*CDIM)          // 3072

// Scratch (device globals; no allocation allowed)
__device__ alignas(16) __nv_bfloat16 g_qh[BATCH*NHEAD*SEQ*HDIM], g_ql[BATCH*NHEAD*SEQ*HDIM];
__device__ alignas(16) __nv_bfloat16 g_kh[BATCH*NHEAD*SEQ*HDIM], g_kl[BATCH*NHEAD*SEQ*HDIM];
__device__ alignas(16) __nv_bfloat16 g_vh[BATCH*NHEAD*SEQ*HDIM], g_vl[BATCH*NHEAD*SEQ*HDIM];
__device__ alignas(16) __nv_bfloat16 g_xh[BT*CDIM], g_xl[BT*CDIM];          // split x  [M,K]
__device__ alignas(16) __nv_bfloat16 g_yh[BT*CDIM], g_yl[BT*CDIM];          // split y  [M,K]
__device__ alignas(16) __nv_bfloat16 g_wah[CDIM*QKV_N], g_wal[CDIM*QKV_N];  // w_attn [K,N]
__device__ alignas(16) __nv_bfloat16 g_wph[CDIM*CDIM],  g_wpl[CDIM*CDIM];   // w_proj [K,N]

// ---------------------------------------------------------------------------
// Helpers
// ---------------------------------------------------------------------------
__device__ __forceinline__ uint32_t smem_u32(const void* p) {
    return (uint32_t)__cvta_generic_to_shared(p);
}
__device__ __forceinline__ void mma16816(float* c, const uint32_t* a,
                                         uint32_t b0, uint32_t b1) {
    asm volatile(
        "mma.sync.aligned.m16n8k16.row.col.f32.bf16.bf16.f32 "
        "{%0,%1,%2,%3},{%4,%5,%6,%7},{%8,%9},{%0,%1,%2,%3};"
        : "+f"(c[0]), "+f"(c[1]), "+f"(c[2]), "+f"(c[3])
        : "r"(a[0]), "r"(a[1]), "r"(a[2]), "r"(a[3]), "r"(b0), "r"(b1));
}
__device__ __forceinline__ void ldmx4(uint32_t* r, uint32_t addr) {
    asm volatile("ldmatrix.sync.aligned.m8n8.x4.shared.b16 {%0,%1,%2,%3},[%4];"
                 : "=r"(r[0]), "=r"(r[1]), "=r"(r[2]), "=r"(r[3]) : "r"(addr));
}
__device__ __forceinline__ void ldmx2(uint32_t& r0, uint32_t& r1, uint32_t addr) {
    asm volatile("ldmatrix.sync.aligned.m8n8.x2.shared.b16 {%0,%1},[%2];"
                 : "=r"(r0), "=r"(r1) : "r"(addr));
}
__device__ __forceinline__ void ldmx2t(uint32_t& r0, uint32_t& r1, uint32_t addr) {
    asm volatile("ldmatrix.sync.aligned.m8n8.x2.trans.shared.b16 {%0,%1},[%2];"
                 : "=r"(r0), "=r"(r1) : "r"(addr));
}
__device__ __forceinline__ void cp16(uint32_t saddr, const void* g) {
    asm volatile("cp.async.cg.shared.global [%0], [%1], 16;" :: "r"(saddr), "l"(g));
}
__device__ __forceinline__ void cp_commit() { asm volatile("cp.async.commit_group;"); }
template<int Np> __device__ __forceinline__ void cp_wait() {
    asm volatile("cp.async.wait_group %0;" :: "n"(Np));
}
// split fp32 -> (hi, lo) bf16 pair (packed bf162)
__device__ __forceinline__ void split2(__nv_bfloat162* hp, __nv_bfloat162* lp,
                                       float x0, float x1) {
    __nv_bfloat16 h0 = __float2bfloat16(x0);
    __nv_bfloat16 h1 = __float2bfloat16(x1);
    *hp = __nv_bfloat162(h0, h1);
    *lp = __nv_bfloat162(__float2bfloat16(x0 - __bfloat162float(h0)),
                         __float2bfloat16(x1 - __bfloat162float(h1)));
}

// ---------------------------------------------------------------------------
// Prep: split fp32 array into bf16 hi/lo
// ---------------------------------------------------------------------------
__global__ __launch_bounds__(256) void split_fp32(
    const float4* __restrict__ in, __nv_bfloat162* __restrict__ h,
    __nv_bfloat162* __restrict__ l, int n4)
{
    int i = blockIdx.x * 256 + threadIdx.x;
    if (i >= n4) return;
    float4 v = in[i];
    __nv_bfloat162 h0, l0, h1, l1;
    split2(&h0, &l0, v.x, v.y);
    split2(&h1, &l1, v.z, v.w);
    h[i * 2] = h0; h[i * 2 + 1] = h1;
    l[i * 2] = l0; l[i * 2 + 1] = l1;
}

// ---------------------------------------------------------------------------
// bf16-split tensor-core GEMM: C[M,N] = A[M,K] @ B[K,N], fp32-accurate.
// 128x128 tile, BK=32, 8 warps (warp tile 64x32), cp.async double-buffered.
// MMAs issued in 3 dependency-spaced passes (hh, hl, lh).
// EPI=0: plain row-major C. EPI=1: QKV scatter as SPLIT bf16 q/k/v.
// ---------------------------------------------------------------------------
#define STAGE_BYTES 32768   // Ah(8K) Al(8K) Bh(8K) Bl(8K)

template<int EPI>
__global__ __launch_bounds__(256)
void gemm_bf16split(const __nv_bfloat16* __restrict__ Ah,
                    const __nv_bfloat16* __restrict__ Al,
                    const __nv_bfloat16* __restrict__ Bh,
                    const __nv_bfloat16* __restrict__ Bl,
                    float* __restrict__ C, int N, int K)
{
    extern __shared__ char smem[];
    const uint32_t sbase = smem_u32(smem);

    const int t = threadIdx.x, lane = t & 31, w = t >> 5;
    const int m0 = blockIdx.y * 128, n0 = blockIdx.x * 128;
    const int wm = w & 1, wn = w >> 1;

    float acc[4][4][4] = {};

    const int NIT = K / 32;

    auto load_stage = [&](int it, int buf) {
        uint32_t sb = sbase + buf * STAGE_BYTES;
        int k0 = it * 32;
        #pragma unroll
        for (int u = 0; u < 2; ++u) {
            int q = t + u * 256;
            int r = q >> 2, c16 = q & 3;
            uint32_t sc = (uint32_t)(r * 4 + (c16 ^ ((r >> 1) & 3))) * 16;
            size_t go = (size_t)(m0 + r) * K + k0 + c16 * 8;
            cp16(sb + sc,        Ah + go);
            cp16(sb + 8192 + sc, Al + go);
        }
        #pragma unroll
        for (int u = 0; u < 2; ++u) {
            int q = t + u * 256;
            int k = q >> 4, c16 = q & 15;
            uint32_t sc = (uint32_t)(k * 16 + (c16 ^ (k & 7))) * 16;
            size_t go = (size_t)(k0 + k) * N + n0 + c16 * 8;
            cp16(sb + 16384 + sc, Bh + go);
            cp16(sb + 24576 + sc, Bl + go);
        }
    };

    load_stage(0, 0);
    cp_commit();

    for (int it = 0; it < NIT; ++it) {
        if (it + 1 < NIT) {
            load_stage(it + 1, (it + 1) & 1);
            cp_commit();
            cp_wait<1>();
        } else {
            cp_wait<0>();
        }
        __syncthreads();

        uint32_t sb  = sbase + (it & 1) * STAGE_BYTES;
        uint32_t sAh = sb, sAl = sb + 8192, sBh = sb + 16384, sBl = sb + 24576;

        #pragma unroll
        for (int kk = 0; kk < 2; ++kk) {
            uint32_t ah[4][4], al[4][4], bh[4][2], bl[4][2];
            #pragma unroll
            for (int mt = 0; mt < 4; ++mt) {
                int r = wm * 64 + mt * 16 + (lane & 15);
                int c16 = kk * 2 + (lane >> 4);
                uint32_t off = (uint32_t)(r * 4 + (c16 ^ ((r >> 1) & 3))) * 16;
                ldmx4(ah[mt], sAh + off);
                ldmx4(al[mt], sAl + off);
            }
            #pragma unroll
            for (int nt = 0; nt < 4; ++nt) {
                int k = kk * 16 + (lane & 15);
                int c16 = wn * 4 + nt;
                uint32_t off = (uint32_t)(k * 16 + (c16 ^ (k & 7))) * 16;
                ldmx2t(bh[nt][0], bh[nt][1], sBh + off);
                ldmx2t(bl[nt][0], bl[nt][1], sBl + off);
            }
            // dependency-spaced passes: each acc touched once per 16 MMAs
            #pragma unroll
            for (int mt = 0; mt < 4; ++mt)
                #pragma unroll
                for (int nt = 0; nt < 4; ++nt)
                    mma16816(acc[mt][nt], ah[mt], bh[nt][0], bh[nt][1]);
            #pragma unroll
            for (int mt = 0; mt < 4; ++mt)
                #pragma unroll
                for (int nt = 0; nt < 4; ++nt)
                    mma16816(acc[mt][nt], ah[mt], bl[nt][0], bl[nt][1]);
            #pragma unroll
            for (int mt = 0; mt < 4; ++mt)
                #pragma unroll
                for (int nt = 0; nt < 4; ++nt)
                    mma16816(acc[mt][nt], al[mt], bh[nt][0], bh[nt][1]);
        }
        __syncthreads();
    }

    // epilogue
    int g = lane >> 2, qoff = (lane & 3) * 2;
    if (EPI == 0) {
        #pragma unroll
        for (int mt = 0; mt < 4; ++mt) {
            int r0 = m0 + wm * 64 + mt * 16 + g;
            #pragma unroll
            for (int nt = 0; nt < 4; ++nt) {
                int n = n0 + wn * 32 + nt * 8 + qoff;
                *(float2*)(C + (size_t)r0 * N + n) =
                    make_float2(acc[mt][nt][0], acc[mt][nt][1]);
                *(float2*)(C + (size_t)(r0 + 8) * N + n) =
                    make_float2(acc[mt][nt][2], acc[mt][nt][3]);
            }
        }
    } else {
        #pragma unroll
        for (int mt = 0; mt < 4; ++mt) {
            int r = m0 + wm * 64 + mt * 16 + g;
            int b = r >> 11, tt = r & 2047;
            #pragma unroll
            for (int nt = 0; nt < 4; ++nt) {
                int n = n0 + wn * 32 + nt * 8 + qoff;
                int region = n >> 10, c = n & 1023, h = c >> 6, d = c & 63;
                __nv_bfloat16 *ohp, *olp;
                if      (region == 0) { ohp = g_qh; olp = g_ql; }
                else if (region == 1) { ohp = g_kh; olp = g_kl; }
                else                  { ohp = g_vh; olp = g_vl; }
                size_t base = (((size_t)(b * NHEAD + h) * SEQ + tt) * HDIM + d);
                __nv_bfloat162 hp, lp;
                split2(&hp, &lp, acc[mt][nt][0], acc[mt][nt][1]);
                *(__nv_bfloat162*)(ohp + base) = hp;
                *(__nv_bfloat162*)(olp + base) = lp;
                split2(&hp, &lp, acc[mt][nt][2], acc[mt][nt][3]);
                *(__nv_bfloat162*)(ohp + base + 8 * HDIM) = hp;
                *(__nv_bfloat162*)(olp + base + 8 * HDIM) = lp;
            }
        }
    }
}

// ---------------------------------------------------------------------------
// Flash attention: pre-split bf16 q/k/v, double-buffered cp.async K/V tiles,
// dependency-spaced MMA passes.
// ---------------------------------------------------------------------------
#define LDK 72                  // padded smem row (bf16 elems)
#define ABUF 9216               // bytes per 64xLDK bf16 array
#define TILE_BYTES (4*ABUF)     // kh|kl|vh|vl
#define ATTN_SMEM (2*TILE_BYTES)

__global__ __launch_bounds__(256) void flash_attn_mma()
{
    extern __shared__ char dynsm[];
    const uint32_t smb = smem_u32(dynsm);

    int t = threadIdx.x, lane = t & 31, w = t >> 5;
    int bx = blockIdx.x, bh2 = blockIdx.y;
    int b = bh2 >> 4, h = bh2 & 15;

    size_t headoff = (size_t)bh2 * SEQ * HDIM;

    // ---- stage Q tile (128x64 hi/lo) via cp.async into buffer 0 space
    {
        const __nv_bfloat16* qhg = g_qh + headoff + (size_t)bx * 128 * HDIM;
        const __nv_bfloat16* qlg = g_ql + headoff + (size_t)bx * 128 * HDIM;
        #pragma unroll
        for (int i = 0; i < 4; ++i) {
            int q = t + i * 256;
            int r = q >> 3, c8 = q & 7;
            uint32_t soff = (uint32_t)(r * LDK + c8 * 8) * 2;
            cp16(smb + soff,             qhg + r * 64 + c8 * 8);
            cp16(smb + 2 * ABUF + soff,  qlg + r * 64 + c8 * 8);
        }
    }
    cp_commit();
    cp_wait<0>();
    __syncthreads();

    uint32_t qhf[4][4], qlf[4][4];
    {
        int row = w * 16 + (lane & 15);
        #pragma unroll
        for (int kt = 0; kt < 4; ++kt) {
            int col = kt * 16 + (lane >> 4) * 8;
            uint32_t a = smb + (uint32_t)(row * LDK + col) * 2;
            ldmx4(qhf[kt], a);
            ldmx4(qlf[kt], a + 2 * ABUF);
        }
    }
    __syncthreads();

    float oacc[8][4];
    #pragma unroll
    for (int i = 0; i < 8; ++i) { oacc[i][0]=0.f; oacc[i][1]=0.f; oacc[i][2]=0.f; oacc[i][3]=0.f; }

    float m0 = -1e30f, m1 = -1e30f, l0 = 0.f, l1 = 0.f;
    int g    = lane >> 2;
    int qoff = (lane & 3) * 2;
    int rw   = bx * 128 + w * 16;
    const float scale = 0.125f;

    auto load_kv = [&](int kt, int buf) {
        size_t tb = headoff + (size_t)kt * 64 * HDIM;
        uint32_t bb = smb + buf * TILE_BYTES;
        #pragma unroll
        for (int i = 0; i < 2; ++i) {
            int q = t + i * 256;
            int r = q >> 3, c8 = q & 7;
            uint32_t soff = (uint32_t)(r * LDK + c8 * 8) * 2;
            size_t go = tb + r * 64 + c8 * 8;
            cp16(bb + soff,            g_kh + go);
            cp16(bb + ABUF + soff,     g_kl + go);
            cp16(bb + 2 * ABUF + soff, g_vh + go);
            cp16(bb + 3 * ABUF + soff, g_vl + go);
        }
    };

    int ntiles = 2 * bx + 2;
    load_kv(0, 0);
    cp_commit();

    for (int kt = 0; kt < ntiles; ++kt) {
        if (kt + 1 < ntiles) {
            load_kv(kt + 1, (kt + 1) & 1);
            cp_commit();
            cp_wait<1>();
        } else {
            cp_wait<0>();
        }
        __syncthreads();

        uint32_t bb = smb + (kt & 1) * TILE_BYTES;

        if (kt * 64 <= rw + 15) {
            // ---- S = Q K^T, 3-term split, pass-reordered
            float sacc[8][4];
            #pragma unroll
            for (int i = 0; i < 8; ++i) { sacc[i][0]=0.f; sacc[i][1]=0.f; sacc[i][2]=0.f; sacc[i][3]=0.f; }

            #pragma unroll
            for (int c = 0; c < 4; ++c) {
                int col = c * 16 + (((lane & 15) >> 3)) * 8;
                int keyrb = lane & 7;
                uint32_t kfh[8][2], kfl[8][2];
                #pragma unroll
                for (int nt = 0; nt < 8; ++nt) {
                    uint32_t a = bb + (uint32_t)((nt * 8 + keyrb) * LDK + col) * 2;
                    ldmx2(kfh[nt][0], kfh[nt][1], a);
                    ldmx2(kfl[nt][0], kfl[nt][1], a + ABUF);
                }
                #pragma unroll
                for (int nt = 0; nt < 8; ++nt)
                    mma16816(sacc[nt], qhf[c], kfh[nt][0], kfh[nt][1]);
                #pragma unroll
                for (int nt = 0; nt < 8; ++nt)
                    mma16816(sacc[nt], qhf[c], kfl[nt][0], kfl[nt][1]);
                #pragma unroll
                for (int nt = 0; nt < 8; ++nt)
                    mma16816(sacc[nt], qlf[c], kfh[nt][0], kfh[nt][1]);
            }

            // ---- scale + causal mask + row max
            int i0 = rw + g, i1 = rw + g + 8;
            float mt0 = -1e30f, mt1 = -1e30f;
            #pragma unroll
            for (int nt = 0; nt < 8; ++nt) {
                int j0 = kt * 64 + nt * 8 + qoff;
                float s0 = sacc[nt][0] * scale;
                float s1 = sacc[nt][1] * scale;
                float s2 = sacc[nt][2] * scale;
                float s3 = sacc[nt][3] * scale;
                if (j0     > i0) s0 = -1e30f;
                if (j0 + 1 > i0) s1 = -1e30f;
                if (j0     > i1) s2 = -1e30f;
                if (j0 + 1 > i1) s3 = -1e30f;
                sacc[nt][0] = s0; sacc[nt][1] = s1;
                sacc[nt][2] = s2; sacc[nt][3] = s3;
                mt0 = fmaxf(mt0, fmaxf(s0, s1));
                mt1 = fmaxf(mt1, fmaxf(s2, s3));
            }
            mt0 = fmaxf(mt0, __shfl_xor_sync(0xffffffffu, mt0, 1));
            mt0 = fmaxf(mt0, __shfl_xor_sync(0xffffffffu, mt0, 2));
            mt1 = fmaxf(mt1, __shfl_xor_sync(0xffffffffu, mt1, 1));
            mt1 = fmaxf(mt1, __shfl_xor_sync(0xffffffffu, mt1, 2));

            float mn0 = fmaxf(m0, mt0), mn1 = fmaxf(m1, mt1);
            float a0 = __expf(m0 - mn0), a1 = __expf(m1 - mn1);
            m0 = mn0; m1 = mn1;
            l0 *= a0;  l1 *= a1;
            #pragma unroll
            for (int nt = 0; nt < 8; ++nt) {
                oacc[nt][0] *= a0; oacc[nt][1] *= a0;
                oacc[nt][2] *= a1; oacc[nt][3] *= a1;
            }

            // ---- P = exp(S - m), O += P V (pass-reordered)
            #pragma unroll
            for (int c2 = 0; c2 < 4; ++c2) {
                float p0 = __expf(sacc[2*c2  ][0] - m0);
                float p1 = __expf(sacc[2*c2  ][1] - m0);
                float p2 = __expf(sacc[2*c2  ][2] - m1);
                float p3 = __expf(sacc[2*c2  ][3] - m1);
                float p4 = __expf(sacc[2*c2+1][0] - m0);
                float p5 = __expf(sacc[2*c2+1][1] - m0);
                float p6 = __expf(sacc[2*c2+1][2] - m1);
                float p7 = __expf(sacc[2*c2+1][3] - m1);
                l0 += p0 + p1 + p4 + p5;
                l1 += p2 + p3 + p6 + p7;

                uint32_t phr[4], plr[4];
                {
                    __nv_bfloat162 hp, lp;
                    split2(&hp, &lp, p0, p1); phr[0] = *(uint32_t*)&hp; plr[0] = *(uint32_t*)&lp;
                    split2(&hp, &lp, p2, p3); phr[1] = *(uint32_t*)&hp; plr[1] = *(uint32_t*)&lp;
                    split2(&hp, &lp, p4, p5); phr[2] = *(uint32_t*)&hp; plr[2] = *(uint32_t*)&lp;
                    split2(&hp, &lp, p6, p7); phr[3] = *(uint32_t*)&hp; plr[3] = *(uint32_t*)&lp;
                }

                int keyr = c2 * 16 + (lane & 15);
                uint32_t vfh[8][2], vfl[8][2];
                #pragma unroll
                for (int nt = 0; nt < 8; ++nt) {
                    uint32_t a = bb + 2 * ABUF + (uint32_t)(keyr * LDK + nt * 8) * 2;
                    ldmx2t(vfh[nt][0], vfh[nt][1], a);
                    ldmx2t(vfl[nt][0], vfl[nt][1], a + ABUF);
                }
                #pragma unroll
                for (int nt = 0; nt < 8; ++nt)
                    mma16816(oacc[nt], phr, vfh[nt][0], vfh[nt][1]);
                #pragma unroll
                for (int nt = 0; nt < 8; ++nt)
                    mma16816(oacc[nt], phr, vfl[nt][0], vfl[nt][1]);
                #pragma unroll
                for (int nt = 0; nt < 8; ++nt)
                    mma16816(oacc[nt], plr, vfh[nt][0], vfh[nt][1]);
            }
        }
        __syncthreads();
    }

    // ---- finalize
    l0 += __shfl_xor_sync(0xffffffffu, l0, 1);
    l0 += __shfl_xor_sync(0xffffffffu, l0, 2);
    l1 += __shfl_xor_sync(0xffffffffu, l1, 1);
    l1 += __shfl_xor_sync(0xffffffffu, l1, 2);
    float inv0 = 1.f / l0, inv1 = 1.f / l1;

    size_t o0 = ((size_t)(b * SEQ + rw + g    )) * CDIM + h * 64;
    size_t o1 = ((size_t)(b * SEQ + rw + g + 8)) * CDIM + h * 64;
    #pragma unroll
    for (int nt = 0; nt < 8; ++nt) {
        __nv_bfloat162 hp, lp;
        split2(&hp, &lp, oacc[nt][0] * inv0, oacc[nt][1] * inv0);
        *(__nv_bfloat162*)(g_yh + o0 + nt * 8 + qoff) = hp;
        *(__nv_bfloat162*)(g_yl + o0 + nt * 8 + qoff) = lp;
        split2(&hp, &lp, oacc[nt][2] * inv1, oacc[nt][3] * inv1);
        *(__nv_bfloat162*)(g_yh + o1 + nt * 8 + qoff) = hp;
        *(__nv_bfloat162*)(g_yl + o1 + nt * 8 + qoff) = lp;
    }
}

// ---------------------------------------------------------------------------
// Launch: splits -> QKV GEMM -> attention -> proj GEMM
// ---------------------------------------------------------------------------
extern "C" void kernel_launch(void* const* d_in, const int* in_sizes, int n_in,
                              void* d_out, int out_size)
{
    const float* x      = (const float*)d_in[0];
    const float* w_attn = (const float*)d_in[1];
    const float* w_proj = (const float*)d_in[2];
    float* out = (float*)d_out;

    __nv_bfloat16 *xh, *xl, *yh, *yl, *wah, *wal, *wph, *wpl;
    cudaGetSymbolAddress((void**)&xh,  g_xh);  cudaGetSymbolAddress((void**)&xl,  g_xl);
    cudaGetSymbolAddress((void**)&yh,  g_yh);  cudaGetSymbolAddress((void**)&yl,  g_yl);
    cudaGetSymbolAddress((void**)&wah, g_wah); cudaGetSymbolAddress((void**)&wal, g_wal);
    cudaGetSymbolAddress((void**)&wph, g_wph); cudaGetSymbolAddress((void**)&wpl, g_wpl);

    cudaFuncSetAttribute(gemm_bf16split<0>,
                         cudaFuncAttributeMaxDynamicSharedMemorySize, 2 * STAGE_BYTES);
    cudaFuncSetAttribute(gemm_bf16split<1>,
                         cudaFuncAttributeMaxDynamicSharedMemorySize, 2 * STAGE_BYTES);
    cudaFuncSetAttribute(flash_attn_mma,
                         cudaFuncAttributeMaxDynamicSharedMemorySize, ATTN_SMEM);

    // splits
    split_fp32<<<(BT * CDIM / 4) / 256, 256>>>(
        (const float4*)x, (__nv_bfloat162*)xh, (__nv_bfloat162*)xl, BT * CDIM / 4);
    split_fp32<<<(CDIM * QKV_N / 4) / 256, 256>>>(
        (const float4*)w_attn, (__nv_bfloat162*)wah, (__nv_bfloat162*)wal, CDIM * QKV_N / 4);
    split_fp32<<<(CDIM * CDIM / 4) / 256, 256>>>(
        (const float4*)w_proj, (__nv_bfloat162*)wph, (__nv_bfloat162*)wpl, CDIM * CDIM / 4);

    // 1) QKV GEMM: [8192,1024]@[1024,3072] -> split q/k/v scatter
    {
        dim3 grid(QKV_N / 128, BT / 128);   // 24 x 64
        gemm_bf16split<1><<<grid, 256, 2 * STAGE_BYTES>>>(xh, xl, wah, wal,
                                                          nullptr, QKV_N, CDIM);
    }
    // 2) attention
    {
        dim3 grid(SEQ / 128, BATCH * NHEAD);  // 16 x 64
        flash_attn_mma<<<grid, 256, ATTN_SMEM>>>();
    }
    // 3) proj GEMM: [8192,1024]@[1024,1024] -> out
    {
        dim3 grid(CDIM / 128, BT / 128);    // 8 x 64
        gemm_bf16split<0><<<grid, 256, 2 * STAGE_BYTES>>>(yh, yl, wph, wpl,
                                                          out, CDIM, CDIM);
    }
}

// round 6
// speedup vs baseline: 6.5386x; 1.4472x over previous
#include <cuda_runtime.h>
#include <cuda_fp16.h>
#include <cstddef>
#include <cstdint>

// Problem constants
#define BATCH 4
#define SEQ   2048
#define CDIM  1024
#define NHEAD 16
#define HDIM  64
#define BT    (BATCH*SEQ)       // 8192
#define QKV_N (3*CDIM)          // 3072

// Scratch (device globals; no allocation allowed)
__device__ alignas(16) __half g_qh[BATCH*NHEAD*SEQ*HDIM], g_ql[BATCH*NHEAD*SEQ*HDIM];
__device__ alignas(16) __half g_kh[BATCH*NHEAD*SEQ*HDIM];
__device__ alignas(16) __half g_vh[BATCH*NHEAD*SEQ*HDIM];
__device__ alignas(16) __half g_xh[BT*CDIM], g_xl[BT*CDIM];    // split x [M,K]
__device__ alignas(16) __half g_yh[BT*CDIM], g_yl[BT*CDIM];    // split y [M,K]
__device__ alignas(16) __half g_wah[CDIM*QKV_N];               // w_attn hi [K,N]
__device__ alignas(16) __half g_wph[CDIM*CDIM];                // w_proj hi [K,N]

// ---------------------------------------------------------------------------
// Helpers
// ---------------------------------------------------------------------------
__device__ __forceinline__ uint32_t smem_u32(const void* p) {
    return (uint32_t)__cvta_generic_to_shared(p);
}
__device__ __forceinline__ void mma16816(float* c, const uint32_t* a,
                                         uint32_t b0, uint32_t b1) {
    asm volatile(
        "mma.sync.aligned.m16n8k16.row.col.f32.f16.f16.f32 "
        "{%0,%1,%2,%3},{%4,%5,%6,%7},{%8,%9},{%0,%1,%2,%3};"
        : "+f"(c[0]), "+f"(c[1]), "+f"(c[2]), "+f"(c[3])
        : "r"(a[0]), "r"(a[1]), "r"(a[2]), "r"(a[3]), "r"(b0), "r"(b1));
}
__device__ __forceinline__ void ldmx4(uint32_t* r, uint32_t addr) {
    asm volatile("ldmatrix.sync.aligned.m8n8.x4.shared.b16 {%0,%1,%2,%3},[%4];"
                 : "=r"(r[0]), "=r"(r[1]), "=r"(r[2]), "=r"(r[3]) : "r"(addr));
}
__device__ __forceinline__ void ldmx2(uint32_t& r0, uint32_t& r1, uint32_t addr) {
    asm volatile("ldmatrix.sync.aligned.m8n8.x2.shared.b16 {%0,%1},[%2];"
                 : "=r"(r0), "=r"(r1) : "r"(addr));
}
__device__ __forceinline__ void ldmx2t(uint32_t& r0, uint32_t& r1, uint32_t addr) {
    asm volatile("ldmatrix.sync.aligned.m8n8.x2.trans.shared.b16 {%0,%1},[%2];"
                 : "=r"(r0), "=r"(r1) : "r"(addr));
}
__device__ __forceinline__ void cp16(uint32_t saddr, const void* g) {
    asm volatile("cp.async.cg.shared.global [%0], [%1], 16;" :: "r"(saddr), "l"(g));
}
__device__ __forceinline__ void cp_commit() { asm volatile("cp.async.commit_group;"); }
template<int Np> __device__ __forceinline__ void cp_wait() {
    asm volatile("cp.async.wait_group %0;" :: "n"(Np));
}
// split fp32 -> (hi, lo) fp16 pair (packed half2)
__device__ __forceinline__ void split2h(__half2* hp, __half2* lp,
                                        float x0, float x1) {
    __half h0 = __float2half_rn(x0);
    __half h1 = __float2half_rn(x1);
    *hp = __halves2half2(h0, h1);
    *lp = __halves2half2(__float2half_rn(x0 - __half2float(h0)),
                         __float2half_rn(x1 - __half2float(h1)));
}

// ---------------------------------------------------------------------------
// Prep kernels
// ---------------------------------------------------------------------------
__global__ __launch_bounds__(256) void split_fp16(
    const float4* __restrict__ in, __half2* __restrict__ h,
    __half2* __restrict__ l, int n4)
{
    int i = blockIdx.x * 256 + threadIdx.x;
    if (i >= n4) return;
    float4 v = in[i];
    __half2 h0, l0, h1, l1;
    split2h(&h0, &l0, v.x, v.y);
    split2h(&h1, &l1, v.z, v.w);
    h[i * 2] = h0; h[i * 2 + 1] = h1;
    l[i * 2] = l0; l[i * 2 + 1] = l1;
}
__global__ __launch_bounds__(256) void conv_fp16(
    const float4* __restrict__ in, __half2* __restrict__ h, int n4)
{
    int i = blockIdx.x * 256 + threadIdx.x;
    if (i >= n4) return;
    float4 v = in[i];
    h[i * 2]     = __floats2half2_rn(v.x, v.y);
    h[i * 2 + 1] = __floats2half2_rn(v.z, v.w);
}

// ---------------------------------------------------------------------------
// fp16 2-term split GEMM: C[M,N] = A[M,K] @ B[K,N], err ~1.4e-4.
// 128x128 tile, BK=32, 8 warps (warp tile 64x32), cp.async double-buffered.
// 2 MMA passes: Ah*Bh + Al*Bh. B is hi-only.
// EPI=0: plain row-major C. EPI=1: QKV scatter (q split hi/lo, k/v hi).
// ---------------------------------------------------------------------------
#define STAGE_BYTES 24576   // Ah(8K) Al(8K) Bh(8K)

template<int EPI>
__global__ __launch_bounds__(256)
void gemm_f16s(const __half* __restrict__ Ah, const __half* __restrict__ Al,
               const __half* __restrict__ Bh,
               float* __restrict__ C, int N, int K)
{
    extern __shared__ char smem[];
    const uint32_t sbase = smem_u32(smem);

    const int t = threadIdx.x, lane = t & 31, w = t >> 5;
    const int m0 = blockIdx.y * 128, n0 = blockIdx.x * 128;
    const int wm = w & 1, wn = w >> 1;

    float acc[4][4][4] = {};
    const int NIT = K / 32;

    auto load_stage = [&](int it, int buf) {
        uint32_t sb = sbase + buf * STAGE_BYTES;
        int k0 = it * 32;
        #pragma unroll
        for (int u = 0; u < 2; ++u) {
            int q = t + u * 256;
            int r = q >> 2, c16 = q & 3;
            uint32_t sc = (uint32_t)(r * 4 + (c16 ^ ((r >> 1) & 3))) * 16;
            size_t go = (size_t)(m0 + r) * K + k0 + c16 * 8;
            cp16(sb + sc,        Ah + go);
            cp16(sb + 8192 + sc, Al + go);
        }
        #pragma unroll
        for (int u = 0; u < 2; ++u) {
            int q = t + u * 256;
            int k = q >> 4, c16 = q & 15;
            uint32_t sc = (uint32_t)(k * 16 + (c16 ^ (k & 7))) * 16;
            size_t go = (size_t)(k0 + k) * N + n0 + c16 * 8;
            cp16(sb + 16384 + sc, Bh + go);
        }
    };

    load_stage(0, 0);
    cp_commit();

    for (int it = 0; it < NIT; ++it) {
        if (it + 1 < NIT) {
            load_stage(it + 1, (it + 1) & 1);
            cp_commit();
            cp_wait<1>();
        } else {
            cp_wait<0>();
        }
        __syncthreads();

        uint32_t sb  = sbase + (it & 1) * STAGE_BYTES;
        uint32_t sAh = sb, sAl = sb + 8192, sBh = sb + 16384;

        #pragma unroll
        for (int kk = 0; kk < 2; ++kk) {
            uint32_t ah[4][4], al[4][4], bh[4][2];
            #pragma unroll
            for (int mt = 0; mt < 4; ++mt) {
                int r = wm * 64 + mt * 16 + (lane & 15);
                int c16 = kk * 2 + (lane >> 4);
                uint32_t off = (uint32_t)(r * 4 + (c16 ^ ((r >> 1) & 3))) * 16;
                ldmx4(ah[mt], sAh + off);
                ldmx4(al[mt], sAl + off);
            }
            #pragma unroll
            for (int nt = 0; nt < 4; ++nt) {
                int k = kk * 16 + (lane & 15);
                int c16 = wn * 4 + nt;
                uint32_t off = (uint32_t)(k * 16 + (c16 ^ (k & 7))) * 16;
                ldmx2t(bh[nt][0], bh[nt][1], sBh + off);
            }
            #pragma unroll
            for (int mt = 0; mt < 4; ++mt)
                #pragma unroll
                for (int nt = 0; nt < 4; ++nt)
                    mma16816(acc[mt][nt], ah[mt], bh[nt][0], bh[nt][1]);
            #pragma unroll
            for (int mt = 0; mt < 4; ++mt)
                #pragma unroll
                for (int nt = 0; nt < 4; ++nt)
                    mma16816(acc[mt][nt], al[mt], bh[nt][0], bh[nt][1]);
        }
        __syncthreads();
    }

    // epilogue
    int g = lane >> 2, qoff = (lane & 3) * 2;
    if (EPI == 0) {
        #pragma unroll
        for (int mt = 0; mt < 4; ++mt) {
            int r0 = m0 + wm * 64 + mt * 16 + g;
            #pragma unroll
            for (int nt = 0; nt < 4; ++nt) {
                int n = n0 + wn * 32 + nt * 8 + qoff;
                *(float2*)(C + (size_t)r0 * N + n) =
                    make_float2(acc[mt][nt][0], acc[mt][nt][1]);
                *(float2*)(C + (size_t)(r0 + 8) * N + n) =
                    make_float2(acc[mt][nt][2], acc[mt][nt][3]);
            }
        }
    } else {
        #pragma unroll
        for (int mt = 0; mt < 4; ++mt) {
            int r = m0 + wm * 64 + mt * 16 + g;
            int b = r >> 11, tt = r & 2047;
            #pragma unroll
            for (int nt = 0; nt < 4; ++nt) {
                int n = n0 + wn * 32 + nt * 8 + qoff;
                int region = n >> 10, c = n & 1023, h = c >> 6, d = c & 63;
                size_t base = (((size_t)(b * NHEAD + h) * SEQ + tt) * HDIM + d);
                if (region == 0) {          // q: split hi/lo
                    __half2 hp, lp;
                    split2h(&hp, &lp, acc[mt][nt][0], acc[mt][nt][1]);
                    *(__half2*)(g_qh + base) = hp;
                    *(__half2*)(g_ql + base) = lp;
                    split2h(&hp, &lp, acc[mt][nt][2], acc[mt][nt][3]);
                    *(__half2*)(g_qh + base + 8 * HDIM) = hp;
                    *(__half2*)(g_ql + base + 8 * HDIM) = lp;
                } else {                    // k/v: hi only
                    __half* dst = (region == 1) ? g_kh : g_vh;
                    *(__half2*)(dst + base) =
                        __floats2half2_rn(acc[mt][nt][0], acc[mt][nt][1]);
                    *(__half2*)(dst + base + 8 * HDIM) =
                        __floats2half2_rn(acc[mt][nt][2], acc[mt][nt][3]);
                }
            }
        }
    }
}

// ---------------------------------------------------------------------------
// Flash attention, fp16 2-term: S = (Qh+Ql)*Kh, O = (Ph+Pl)*Vh.
// Double-buffered cp.async K/V tiles (hi only).
// ---------------------------------------------------------------------------
#define LDK 72                  // padded smem row (fp16 elems)
#define ABUF 9216               // bytes per 64xLDK fp16 array
#define KVTILE (2*ABUF)         // kh | vh

__global__ __launch_bounds__(256) void flash_attn_mma()
{
    __shared__ char sm[2 * KVTILE];       // 36,864 B (also holds Q during init)
    const uint32_t smb = smem_u32(sm);

    int t = threadIdx.x, lane = t & 31, w = t >> 5;
    int bx = blockIdx.x, bh2 = blockIdx.y;
    int b = bh2 >> 4, h = bh2 & 15;

    size_t headoff = (size_t)bh2 * SEQ * HDIM;

    // ---- stage Q tile (128x64 hi/lo) via cp.async
    {
        const __half* qhg = g_qh + headoff + (size_t)bx * 128 * HDIM;
        const __half* qlg = g_ql + headoff + (size_t)bx * 128 * HDIM;
        #pragma unroll
        for (int i = 0; i < 4; ++i) {
            int q = t + i * 256;
            int r = q >> 3, c8 = q & 7;
            uint32_t soff = (uint32_t)(r * LDK + c8 * 8) * 2;
            cp16(smb + soff,         qhg + r * 64 + c8 * 8);
            cp16(smb + 18432 + soff, qlg + r * 64 + c8 * 8);
        }
    }
    cp_commit();
    cp_wait<0>();
    __syncthreads();

    uint32_t qhf[4][4], qlf[4][4];
    {
        int row = w * 16 + (lane & 15);
        #pragma unroll
        for (int kt = 0; kt < 4; ++kt) {
            int col = kt * 16 + (lane >> 4) * 8;
            uint32_t a = smb + (uint32_t)(row * LDK + col) * 2;
            ldmx4(qhf[kt], a);
            ldmx4(qlf[kt], a + 18432);
        }
    }
    __syncthreads();

    float oacc[8][4];
    #pragma unroll
    for (int i = 0; i < 8; ++i) { oacc[i][0]=0.f; oacc[i][1]=0.f; oacc[i][2]=0.f; oacc[i][3]=0.f; }

    float m0 = -1e30f, m1 = -1e30f, l0 = 0.f, l1 = 0.f;
    int g    = lane >> 2;
    int qoff = (lane & 3) * 2;
    int rw   = bx * 128 + w * 16;
    const float scale = 0.125f;

    auto load_kv = [&](int kt, int buf) {
        size_t tb = headoff + (size_t)kt * 64 * HDIM;
        uint32_t bb = smb + buf * KVTILE;
        #pragma unroll
        for (int i = 0; i < 2; ++i) {
            int q = t + i * 256;
            int r = q >> 3, c8 = q & 7;
            uint32_t soff = (uint32_t)(r * LDK + c8 * 8) * 2;
            size_t go = tb + r * 64 + c8 * 8;
            cp16(bb + soff,        g_kh + go);
            cp16(bb + ABUF + soff, g_vh + go);
        }
    };

    int ntiles = 2 * bx + 2;
    load_kv(0, 0);
    cp_commit();

    for (int kt = 0; kt < ntiles; ++kt) {
        if (kt + 1 < ntiles) {
            load_kv(kt + 1, (kt + 1) & 1);
            cp_commit();
            cp_wait<1>();
        } else {
            cp_wait<0>();
        }
        __syncthreads();

        uint32_t bb = smb + (kt & 1) * KVTILE;

        if (kt * 64 <= rw + 15) {
            // ---- S = Q K^T, 2-term
            float sacc[8][4];
            #pragma unroll
            for (int i = 0; i < 8; ++i) { sacc[i][0]=0.f; sacc[i][1]=0.f; sacc[i][2]=0.f; sacc[i][3]=0.f; }

            #pragma unroll
            for (int c = 0; c < 4; ++c) {
                int col = c * 16 + (((lane & 15) >> 3)) * 8;
                int keyrb = lane & 7;
                uint32_t kfh[8][2];
                #pragma unroll
                for (int nt = 0; nt < 8; ++nt) {
                    uint32_t a = bb + (uint32_t)((nt * 8 + keyrb) * LDK + col) * 2;
                    ldmx2(kfh[nt][0], kfh[nt][1], a);
                }
                #pragma unroll
                for (int nt = 0; nt < 8; ++nt)
                    mma16816(sacc[nt], qhf[c], kfh[nt][0], kfh[nt][1]);
                #pragma unroll
                for (int nt = 0; nt < 8; ++nt)
                    mma16816(sacc[nt], qlf[c], kfh[nt][0], kfh[nt][1]);
            }

            // ---- scale + causal mask + row max
            int i0 = rw + g, i1 = rw + g + 8;
            float mt0 = -1e30f, mt1 = -1e30f;
            #pragma unroll
            for (int nt = 0; nt < 8; ++nt) {
                int j0 = kt * 64 + nt * 8 + qoff;
                float s0 = sacc[nt][0] * scale;
                float s1 = sacc[nt][1] * scale;
                float s2 = sacc[nt][2] * scale;
                float s3 = sacc[nt][3] * scale;
                if (j0     > i0) s0 = -1e30f;
                if (j0 + 1 > i0) s1 = -1e30f;
                if (j0     > i1) s2 = -1e30f;
                if (j0 + 1 > i1) s3 = -1e30f;
                sacc[nt][0] = s0; sacc[nt][1] = s1;
                sacc[nt][2] = s2; sacc[nt][3] = s3;
                mt0 = fmaxf(mt0, fmaxf(s0, s1));
                mt1 = fmaxf(mt1, fmaxf(s2, s3));
            }
            mt0 = fmaxf(mt0, __shfl_xor_sync(0xffffffffu, mt0, 1));
            mt0 = fmaxf(mt0, __shfl_xor_sync(0xffffffffu, mt0, 2));
            mt1 = fmaxf(mt1, __shfl_xor_sync(0xffffffffu, mt1, 1));
            mt1 = fmaxf(mt1, __shfl_xor_sync(0xffffffffu, mt1, 2));

            float mn0 = fmaxf(m0, mt0), mn1 = fmaxf(m1, mt1);
            float a0 = __expf(m0 - mn0), a1 = __expf(m1 - mn1);
            m0 = mn0; m1 = mn1;
            l0 *= a0;  l1 *= a1;
            #pragma unroll
            for (int nt = 0; nt < 8; ++nt) {
                oacc[nt][0] *= a0; oacc[nt][1] *= a0;
                oacc[nt][2] *= a1; oacc[nt][3] *= a1;
            }

            // ---- P = exp(S - m), O += P V (2-term on P)
            #pragma unroll
            for (int c2 = 0; c2 < 4; ++c2) {
                float p0 = __expf(sacc[2*c2  ][0] - m0);
                float p1 = __expf(sacc[2*c2  ][1] - m0);
                float p2 = __expf(sacc[2*c2  ][2] - m1);
                float p3 = __expf(sacc[2*c2  ][3] - m1);
                float p4 = __expf(sacc[2*c2+1][0] - m0);
                float p5 = __expf(sacc[2*c2+1][1] - m0);
                float p6 = __expf(sacc[2*c2+1][2] - m1);
                float p7 = __expf(sacc[2*c2+1][3] - m1);
                l0 += p0 + p1 + p4 + p5;
                l1 += p2 + p3 + p6 + p7;

                uint32_t phr[4], plr[4];
                {
                    __half2 hp, lp;
                    split2h(&hp, &lp, p0, p1); phr[0] = *(uint32_t*)&hp; plr[0] = *(uint32_t*)&lp;
                    split2h(&hp, &lp, p2, p3); phr[1] = *(uint32_t*)&hp; plr[1] = *(uint32_t*)&lp;
                    split2h(&hp, &lp, p4, p5); phr[2] = *(uint32_t*)&hp; plr[2] = *(uint32_t*)&lp;
                    split2h(&hp, &lp, p6, p7); phr[3] = *(uint32_t*)&hp; plr[3] = *(uint32_t*)&lp;
                }

                int keyr = c2 * 16 + (lane & 15);
                uint32_t vfh[8][2];
                #pragma unroll
                for (int nt = 0; nt < 8; ++nt) {
                    uint32_t a = bb + ABUF + (uint32_t)(keyr * LDK + nt * 8) * 2;
                    ldmx2t(vfh[nt][0], vfh[nt][1], a);
                }
                #pragma unroll
                for (int nt = 0; nt < 8; ++nt)
                    mma16816(oacc[nt], phr, vfh[nt][0], vfh[nt][1]);
                #pragma unroll
                for (int nt = 0; nt < 8; ++nt)
                    mma16816(oacc[nt], plr, vfh[nt][0], vfh[nt][1]);
            }
        }
        __syncthreads();
    }

    // ---- finalize: write y as split fp16
    l0 += __shfl_xor_sync(0xffffffffu, l0, 1);
    l0 += __shfl_xor_sync(0xffffffffu, l0, 2);
    l1 += __shfl_xor_sync(0xffffffffu, l1, 1);
    l1 += __shfl_xor_sync(0xffffffffu, l1, 2);
    float inv0 = 1.f / l0, inv1 = 1.f / l1;

    size_t o0 = ((size_t)(b * SEQ + rw + g    )) * CDIM + h * 64;
    size_t o1 = ((size_t)(b * SEQ + rw + g + 8)) * CDIM + h * 64;
    #pragma unroll
    for (int nt = 0; nt < 8; ++nt) {
        __half2 hp, lp;
        split2h(&hp, &lp, oacc[nt][0] * inv0, oacc[nt][1] * inv0);
        *(__half2*)(g_yh + o0 + nt * 8 + qoff) = hp;
        *(__half2*)(g_yl + o0 + nt * 8 + qoff) = lp;
        split2h(&hp, &lp, oacc[nt][2] * inv1, oacc[nt][3] * inv1);
        *(__half2*)(g_yh + o1 + nt * 8 + qoff) = hp;
        *(__half2*)(g_yl + o1 + nt * 8 + qoff) = lp;
    }
}

// ---------------------------------------------------------------------------
// Launch: preps -> QKV GEMM -> attention -> proj GEMM
// ---------------------------------------------------------------------------
extern "C" void kernel_launch(void* const* d_in, const int* in_sizes, int n_in,
                              void* d_out, int out_size)
{
    const float* x      = (const float*)d_in[0];
    const float* w_attn = (const float*)d_in[1];
    const float* w_proj = (const float*)d_in[2];
    float* out = (float*)d_out;

    __half *xh, *xl, *yh, *yl, *wah, *wph;
    cudaGetSymbolAddress((void**)&xh,  g_xh);  cudaGetSymbolAddress((void**)&xl,  g_xl);
    cudaGetSymbolAddress((void**)&yh,  g_yh);  cudaGetSymbolAddress((void**)&yl,  g_yl);
    cudaGetSymbolAddress((void**)&wah, g_wah); cudaGetSymbolAddress((void**)&wph, g_wph);

    cudaFuncSetAttribute(gemm_f16s<0>,
                         cudaFuncAttributeMaxDynamicSharedMemorySize, 2 * STAGE_BYTES);
    cudaFuncSetAttribute(gemm_f16s<1>,
                         cudaFuncAttributeMaxDynamicSharedMemorySize, 2 * STAGE_BYTES);

    // preps
    split_fp16<<<(BT * CDIM / 4) / 256, 256>>>(
        (const float4*)x, (__half2*)xh, (__half2*)xl, BT * CDIM / 4);
    conv_fp16<<<(CDIM * QKV_N / 4) / 256, 256>>>(
        (const float4*)w_attn, (__half2*)wah, CDIM * QKV_N / 4);
    conv_fp16<<<(CDIM * CDIM / 4) / 256, 256>>>(
        (const float4*)w_proj, (__half2*)wph, CDIM * CDIM / 4);

    // 1) QKV GEMM: [8192,1024]@[1024,3072] -> q (split) / k / v
    {
        dim3 grid(QKV_N / 128, BT / 128);   // 24 x 64
        gemm_f16s<1><<<grid, 256, 2 * STAGE_BYTES>>>(xh, xl, wah, nullptr, QKV_N, CDIM);
    }
    // 2) attention
    {
        dim3 grid(SEQ / 128, BATCH * NHEAD);  // 16 x 64
        flash_attn_mma<<<grid, 256>>>();
    }
    // 3) proj GEMM: [8192,1024]@[1024,1024] -> out
    {
        dim3 grid(CDIM / 128, BT / 128);    // 8 x 64
        gemm_f16s<0><<<grid, 256, 2 * STAGE_BYTES>>>(yh, yl, wph, out, CDIM, CDIM);
    }
}

// round 7
// speedup vs baseline: 7.4326x; 1.1367x over previous
#include <cuda_runtime.h>
#include <cuda_fp16.h>
#include <cstddef>
#include <cstdint>

// Problem constants
#define BATCH 4
#define SEQ   2048
#define CDIM  1024
#define NHEAD 16
#define HDIM  64
#define BT    (BATCH*SEQ)       // 8192
#define QKV_N (3*CDIM)          // 3072

// Scratch (device globals; no allocation allowed)
__device__ alignas(16) __half g_q[BATCH*NHEAD*SEQ*HDIM];       // fp16 hi
__device__ alignas(16) __half g_k[BATCH*NHEAD*SEQ*HDIM];
__device__ alignas(16) __half g_v[BATCH*NHEAD*SEQ*HDIM];
__device__ alignas(16) __half g_xh[BT*CDIM], g_xl[BT*CDIM];    // split x [M,K]
__device__ alignas(16) __half g_yh[BT*CDIM], g_yl[BT*CDIM];    // split y [M,K]
__device__ alignas(16) __half g_wah[CDIM*QKV_N];               // w_attn hi [K,N]
__device__ alignas(16) __half g_wph[CDIM*CDIM];                // w_proj hi [K,N]

// ---------------------------------------------------------------------------
// Helpers
// ---------------------------------------------------------------------------
__device__ __forceinline__ uint32_t smem_u32(const void* p) {
    return (uint32_t)__cvta_generic_to_shared(p);
}
__device__ __forceinline__ void mma16816(float* c, const uint32_t* a,
                                         uint32_t b0, uint32_t b1) {
    asm volatile(
        "mma.sync.aligned.m16n8k16.row.col.f32.f16.f16.f32 "
        "{%0,%1,%2,%3},{%4,%5,%6,%7},{%8,%9},{%0,%1,%2,%3};"
        : "+f"(c[0]), "+f"(c[1]), "+f"(c[2]), "+f"(c[3])
        : "r"(a[0]), "r"(a[1]), "r"(a[2]), "r"(a[3]), "r"(b0), "r"(b1));
}
__device__ __forceinline__ void ldmx4(uint32_t* r, uint32_t addr) {
    asm volatile("ldmatrix.sync.aligned.m8n8.x4.shared.b16 {%0,%1,%2,%3},[%4];"
                 : "=r"(r[0]), "=r"(r[1]), "=r"(r[2]), "=r"(r[3]) : "r"(addr));
}
__device__ __forceinline__ void ldmx2(uint32_t& r0, uint32_t& r1, uint32_t addr) {
    asm volatile("ldmatrix.sync.aligned.m8n8.x2.shared.b16 {%0,%1},[%2];"
                 : "=r"(r0), "=r"(r1) : "r"(addr));
}
__device__ __forceinline__ void ldmx2t(uint32_t& r0, uint32_t& r1, uint32_t addr) {
    asm volatile("ldmatrix.sync.aligned.m8n8.x2.trans.shared.b16 {%0,%1},[%2];"
                 : "=r"(r0), "=r"(r1) : "r"(addr));
}
__device__ __forceinline__ void cp16(uint32_t saddr, const void* g) {
    asm volatile("cp.async.cg.shared.global [%0], [%1], 16;" :: "r"(saddr), "l"(g));
}
__device__ __forceinline__ void cp_commit() { asm volatile("cp.async.commit_group;"); }
template<int Np> __device__ __forceinline__ void cp_wait() {
    asm volatile("cp.async.wait_group %0;" :: "n"(Np));
}
__device__ __forceinline__ void split2h(__half2* hp, __half2* lp,
                                        float x0, float x1) {
    __half h0 = __float2half_rn(x0);
    __half h1 = __float2half_rn(x1);
    *hp = __halves2half2(h0, h1);
    *lp = __halves2half2(__float2half_rn(x0 - __half2float(h0)),
                         __float2half_rn(x1 - __half2float(h1)));
}

// ---------------------------------------------------------------------------
// Prep kernels
// ---------------------------------------------------------------------------
__global__ __launch_bounds__(256) void split_fp16(
    const float4* __restrict__ in, __half2* __restrict__ h,
    __half2* __restrict__ l, int n4)
{
    int i = blockIdx.x * 256 + threadIdx.x;
    if (i >= n4) return;
    float4 v = in[i];
    __half2 h0, l0, h1, l1;
    split2h(&h0, &l0, v.x, v.y);
    split2h(&h1, &l1, v.z, v.w);
    h[i * 2] = h0; h[i * 2 + 1] = h1;
    l[i * 2] = l0; l[i * 2 + 1] = l1;
}
__global__ __launch_bounds__(256) void conv_fp16(
    const float4* __restrict__ in, __half2* __restrict__ h, int n4)
{
    int i = blockIdx.x * 256 + threadIdx.x;
    if (i >= n4) return;
    float4 v = in[i];
    h[i * 2]     = __floats2half2_rn(v.x, v.y);
    h[i * 2 + 1] = __floats2half2_rn(v.z, v.w);
}

// ---------------------------------------------------------------------------
// fp16 split-A GEMM: C[M,N] = (Ah+Al)[M,K] @ Bh[K,N].
// CTA tile 128x256, warp tile 64x64 (8 warps, 2m x 4n), BK=32,
// cp.async double-buffered, XOR-swizzled smem.
// A fragments loaded hi, MMA pass, then lo into SAME regs, second pass
// (keeps register peak at single-pass level).
// EPI=0: plain fp32 C. EPI=1: QKV scatter as plain fp16 q/k/v.
// ---------------------------------------------------------------------------
#define STAGE_BYTES 32768   // Ah(8K) Al(8K) Bh(16K)

template<int EPI>
__global__ __launch_bounds__(256)
void gemm_f16s(const __half* __restrict__ Ah, const __half* __restrict__ Al,
               const __half* __restrict__ Bh,
               float* __restrict__ C, int N, int K)
{
    extern __shared__ char smem[];
    const uint32_t sbase = smem_u32(smem);

    const int t = threadIdx.x, lane = t & 31, w = t >> 5;
    const int m0 = blockIdx.y * 128, n0 = blockIdx.x * 256;
    const int wm = w & 1, wn = w >> 1;

    float acc[4][8][4] = {};
    const int NIT = K / 32;

    auto load_stage = [&](int it, int buf) {
        uint32_t sb = sbase + buf * STAGE_BYTES;
        int k0 = it * 32;
        // A: 128 rows x 4 chunks (hi + lo), 2 chunks/thread each
        #pragma unroll
        for (int u = 0; u < 2; ++u) {
            int q = t + u * 256;
            int r = q >> 2, c16 = q & 3;
            uint32_t sc = (uint32_t)(r * 4 + (c16 ^ ((r >> 1) & 3))) * 16;
            size_t go = (size_t)(m0 + r) * K + k0 + c16 * 8;
            cp16(sb + sc,        Ah + go);
            cp16(sb + 8192 + sc, Al + go);
        }
        // B: 32 rows x 32 chunks, 4 chunks/thread
        #pragma unroll
        for (int u = 0; u < 4; ++u) {
            int q = t + u * 256;
            int k = q >> 5, c = q & 31;
            uint32_t sc = (uint32_t)(k * 32 + (c ^ (k & 7))) * 16;
            size_t go = (size_t)(k0 + k) * N + n0 + c * 8;
            cp16(sb + 16384 + sc, Bh + go);
        }
    };

    load_stage(0, 0);
    cp_commit();

    for (int it = 0; it < NIT; ++it) {
        if (it + 1 < NIT) {
            load_stage(it + 1, (it + 1) & 1);
            cp_commit();
            cp_wait<1>();
        } else {
            cp_wait<0>();
        }
        __syncthreads();

        uint32_t sb  = sbase + (it & 1) * STAGE_BYTES;
        uint32_t sAh = sb, sAl = sb + 8192, sBh = sb + 16384;

        #pragma unroll
        for (int kk = 0; kk < 2; ++kk) {
            uint32_t ar[4][4], bf[8][2];
            uint32_t offA[4];
            #pragma unroll
            for (int mt = 0; mt < 4; ++mt) {
                int r = wm * 64 + mt * 16 + (lane & 15);
                int c16 = kk * 2 + (lane >> 4);
                offA[mt] = (uint32_t)(r * 4 + (c16 ^ ((r >> 1) & 3))) * 16;
                ldmx4(ar[mt], sAh + offA[mt]);
            }
            #pragma unroll
            for (int nt = 0; nt < 8; ++nt) {
                int k = kk * 16 + (lane & 15);
                int c = wn * 8 + nt;
                uint32_t off = (uint32_t)(k * 32 + (c ^ (k & 7))) * 16;
                ldmx2t(bf[nt][0], bf[nt][1], sBh + off);
            }
            #pragma unroll
            for (int mt = 0; mt < 4; ++mt)
                #pragma unroll
                for (int nt = 0; nt < 8; ++nt)
                    mma16816(acc[mt][nt], ar[mt], bf[nt][0], bf[nt][1]);
            // lo pass: overwrite A fragments, same B
            #pragma unroll
            for (int mt = 0; mt < 4; ++mt)
                ldmx4(ar[mt], sAl + offA[mt]);
            #pragma unroll
            for (int mt = 0; mt < 4; ++mt)
                #pragma unroll
                for (int nt = 0; nt < 8; ++nt)
                    mma16816(acc[mt][nt], ar[mt], bf[nt][0], bf[nt][1]);
        }
        __syncthreads();
    }

    // epilogue
    int g = lane >> 2, qoff = (lane & 3) * 2;
    if (EPI == 0) {
        #pragma unroll
        for (int mt = 0; mt < 4; ++mt) {
            int r0 = m0 + wm * 64 + mt * 16 + g;
            #pragma unroll
            for (int nt = 0; nt < 8; ++nt) {
                int n = n0 + wn * 64 + nt * 8 + qoff;
                *(float2*)(C + (size_t)r0 * N + n) =
                    make_float2(acc[mt][nt][0], acc[mt][nt][1]);
                *(float2*)(C + (size_t)(r0 + 8) * N + n) =
                    make_float2(acc[mt][nt][2], acc[mt][nt][3]);
            }
        }
    } else {
        int n_first = n0 + wn * 64;
        int region = n_first >> 10;
        int h = (n_first & 1023) >> 6;
        __half* dst = (region == 0) ? g_q : (region == 1) ? g_k : g_v;
        #pragma unroll
        for (int mt = 0; mt < 4; ++mt) {
            int r = m0 + wm * 64 + mt * 16 + g;
            int b = r >> 11, tt = r & 2047;
            size_t base = ((size_t)(b * NHEAD + h) * SEQ + tt) * HDIM;
            #pragma unroll
            for (int nt = 0; nt < 8; ++nt) {
                int d = nt * 8 + qoff;
                *(__half2*)(dst + base + d) =
                    __floats2half2_rn(acc[mt][nt][0], acc[mt][nt][1]);
                *(__half2*)(dst + base + 8 * HDIM + d) =
                    __floats2half2_rn(acc[mt][nt][2], acc[mt][nt][3]);
            }
        }
    }
}

// ---------------------------------------------------------------------------
// Flash attention, single-pass fp16: S = Q*K^T, O = P*V, fp32 softmax/accum.
// Double-buffered cp.async K/V tiles. Writes y as split fp16 hi/lo.
// ---------------------------------------------------------------------------
#define LDK 72                  // padded smem row (fp16 elems)
#define ABUF 9216               // bytes per 64xLDK fp16 array
#define KVTILE (2*ABUF)         // kh | vh

__global__ __launch_bounds__(256) void flash_attn_mma()
{
    __shared__ char sm[2 * KVTILE];       // 36,864 B (Q staged here first)
    const uint32_t smb = smem_u32(sm);

    int t = threadIdx.x, lane = t & 31, w = t >> 5;
    int bx = blockIdx.x, bh2 = blockIdx.y;
    int b = bh2 >> 4, h = bh2 & 15;

    size_t headoff = (size_t)bh2 * SEQ * HDIM;

    // ---- stage Q tile (128x64, hi only)
    {
        const __half* qg = g_q + headoff + (size_t)bx * 128 * HDIM;
        #pragma unroll
        for (int i = 0; i < 4; ++i) {
            int q = t + i * 256;
            int r = q >> 3, c8 = q & 7;
            uint32_t soff = (uint32_t)(r * LDK + c8 * 8) * 2;
            cp16(smb + soff, qg + r * 64 + c8 * 8);
        }
    }
    cp_commit();
    cp_wait<0>();
    __syncthreads();

    uint32_t qf[4][4];
    {
        int row = w * 16 + (lane & 15);
        #pragma unroll
        for (int kt = 0; kt < 4; ++kt) {
            int col = kt * 16 + (lane >> 4) * 8;
            ldmx4(qf[kt], smb + (uint32_t)(row * LDK + col) * 2);
        }
    }
    __syncthreads();

    float oacc[8][4];
    #pragma unroll
    for (int i = 0; i < 8; ++i) { oacc[i][0]=0.f; oacc[i][1]=0.f; oacc[i][2]=0.f; oacc[i][3]=0.f; }

    float m0 = -1e30f, m1 = -1e30f, l0 = 0.f, l1 = 0.f;
    int g    = lane >> 2;
    int qoff = (lane & 3) * 2;
    int rw   = bx * 128 + w * 16;
    const float scale = 0.125f;

    auto load_kv = [&](int kt, int buf) {
        size_t tb = headoff + (size_t)kt * 64 * HDIM;
        uint32_t bb = smb + buf * KVTILE;
        #pragma unroll
        for (int i = 0; i < 2; ++i) {
            int q = t + i * 256;
            int r = q >> 3, c8 = q & 7;
            uint32_t soff = (uint32_t)(r * LDK + c8 * 8) * 2;
            size_t go = tb + r * 64 + c8 * 8;
            cp16(bb + soff,        g_k + go);
            cp16(bb + ABUF + soff, g_v + go);
        }
    };

    int ntiles = 2 * bx + 2;
    load_kv(0, 0);
    cp_commit();

    for (int kt = 0; kt < ntiles; ++kt) {
        if (kt + 1 < ntiles) {
            load_kv(kt + 1, (kt + 1) & 1);
            cp_commit();
            cp_wait<1>();
        } else {
            cp_wait<0>();
        }
        __syncthreads();

        uint32_t bb = smb + (kt & 1) * KVTILE;

        if (kt * 64 <= rw + 15) {
            // ---- S = Q K^T (single pass)
            float sacc[8][4];
            #pragma unroll
            for (int i = 0; i < 8; ++i) { sacc[i][0]=0.f; sacc[i][1]=0.f; sacc[i][2]=0.f; sacc[i][3]=0.f; }

            #pragma unroll
            for (int c = 0; c < 4; ++c) {
                int col = c * 16 + (((lane & 15) >> 3)) * 8;
                int keyrb = lane & 7;
                uint32_t kf[8][2];
                #pragma unroll
                for (int nt = 0; nt < 8; ++nt)
                    ldmx2(kf[nt][0], kf[nt][1],
                          bb + (uint32_t)((nt * 8 + keyrb) * LDK + col) * 2);
                #pragma unroll
                for (int nt = 0; nt < 8; ++nt)
                    mma16816(sacc[nt], qf[c], kf[nt][0], kf[nt][1]);
            }

            // ---- scale + causal mask + row max
            int i0 = rw + g, i1 = rw + g + 8;
            float mt0 = -1e30f, mt1 = -1e30f;
            #pragma unroll
            for (int nt = 0; nt < 8; ++nt) {
                int j0 = kt * 64 + nt * 8 + qoff;
                float s0 = sacc[nt][0] * scale;
                float s1 = sacc[nt][1] * scale;
                float s2 = sacc[nt][2] * scale;
                float s3 = sacc[nt][3] * scale;
                if (j0     > i0) s0 = -1e30f;
                if (j0 + 1 > i0) s1 = -1e30f;
                if (j0     > i1) s2 = -1e30f;
                if (j0 + 1 > i1) s3 = -1e30f;
                sacc[nt][0] = s0; sacc[nt][1] = s1;
                sacc[nt][2] = s2; sacc[nt][3] = s3;
                mt0 = fmaxf(mt0, fmaxf(s0, s1));
                mt1 = fmaxf(mt1, fmaxf(s2, s3));
            }
            mt0 = fmaxf(mt0, __shfl_xor_sync(0xffffffffu, mt0, 1));
            mt0 = fmaxf(mt0, __shfl_xor_sync(0xffffffffu, mt0, 2));
            mt1 = fmaxf(mt1, __shfl_xor_sync(0xffffffffu, mt1, 1));
            mt1 = fmaxf(mt1, __shfl_xor_sync(0xffffffffu, mt1, 2));

            float mn0 = fmaxf(m0, mt0), mn1 = fmaxf(m1, mt1);
            float a0 = __expf(m0 - mn0), a1 = __expf(m1 - mn1);
            m0 = mn0; m1 = mn1;
            l0 *= a0;  l1 *= a1;
            #pragma unroll
            for (int nt = 0; nt < 8; ++nt) {
                oacc[nt][0] *= a0; oacc[nt][1] *= a0;
                oacc[nt][2] *= a1; oacc[nt][3] *= a1;
            }

            // ---- P = exp(S - m), O += P V (single pass)
            #pragma unroll
            for (int c2 = 0; c2 < 4; ++c2) {
                float p0 = __expf(sacc[2*c2  ][0] - m0);
                float p1 = __expf(sacc[2*c2  ][1] - m0);
                float p2 = __expf(sacc[2*c2  ][2] - m1);
                float p3 = __expf(sacc[2*c2  ][3] - m1);
                float p4 = __expf(sacc[2*c2+1][0] - m0);
                float p5 = __expf(sacc[2*c2+1][1] - m0);
                float p6 = __expf(sacc[2*c2+1][2] - m1);
                float p7 = __expf(sacc[2*c2+1][3] - m1);
                l0 += p0 + p1 + p4 + p5;
                l1 += p2 + p3 + p6 + p7;

                uint32_t pr[4];
                {
                    __half2 hp;
                    hp = __floats2half2_rn(p0, p1); pr[0] = *(uint32_t*)&hp;
                    hp = __floats2half2_rn(p2, p3); pr[1] = *(uint32_t*)&hp;
                    hp = __floats2half2_rn(p4, p5); pr[2] = *(uint32_t*)&hp;
                    hp = __floats2half2_rn(p6, p7); pr[3] = *(uint32_t*)&hp;
                }

                int keyr = c2 * 16 + (lane & 15);
                uint32_t vf[8][2];
                #pragma unroll
                for (int nt = 0; nt < 8; ++nt)
                    ldmx2t(vf[nt][0], vf[nt][1],
                           bb + ABUF + (uint32_t)(keyr * LDK + nt * 8) * 2);
                #pragma unroll
                for (int nt = 0; nt < 8; ++nt)
                    mma16816(oacc[nt], pr, vf[nt][0], vf[nt][1]);
            }
        }
        __syncthreads();
    }

    // ---- finalize: write y as split fp16 (proj A needs hi/lo)
    l0 += __shfl_xor_sync(0xffffffffu, l0, 1);
    l0 += __shfl_xor_sync(0xffffffffu, l0, 2);
    l1 += __shfl_xor_sync(0xffffffffu, l1, 1);
    l1 += __shfl_xor_sync(0xffffffffu, l1, 2);
    float inv0 = 1.f / l0, inv1 = 1.f / l1;

    size_t o0 = ((size_t)(b * SEQ + rw + g    )) * CDIM + h * 64;
    size_t o1 = ((size_t)(b * SEQ + rw + g + 8)) * CDIM + h * 64;
    #pragma unroll
    for (int nt = 0; nt < 8; ++nt) {
        __half2 hp, lp;
        split2h(&hp, &lp, oacc[nt][0] * inv0, oacc[nt][1] * inv0);
        *(__half2*)(g_yh + o0 + nt * 8 + qoff) = hp;
        *(__half2*)(g_yl + o0 + nt * 8 + qoff) = lp;
        split2h(&hp, &lp, oacc[nt][2] * inv1, oacc[nt][3] * inv1);
        *(__half2*)(g_yh + o1 + nt * 8 + qoff) = hp;
        *(__half2*)(g_yl + o1 + nt * 8 + qoff) = lp;
    }
}

// ---------------------------------------------------------------------------
// Launch: preps -> QKV GEMM -> attention -> proj GEMM
// ---------------------------------------------------------------------------
extern "C" void kernel_launch(void* const* d_in, const int* in_sizes, int n_in,
                              void* d_out, int out_size)
{
    const float* x      = (const float*)d_in[0];
    const float* w_attn = (const float*)d_in[1];
    const float* w_proj = (const float*)d_in[2];
    float* out = (float*)d_out;

    __half *xh, *xl, *yh, *yl, *wah, *wph;
    cudaGetSymbolAddress((void**)&xh,  g_xh);  cudaGetSymbolAddress((void**)&xl,  g_xl);
    cudaGetSymbolAddress((void**)&yh,  g_yh);  cudaGetSymbolAddress((void**)&yl,  g_yl);
    cudaGetSymbolAddress((void**)&wah, g_wah); cudaGetSymbolAddress((void**)&wph, g_wph);

    cudaFuncSetAttribute(gemm_f16s<0>,
                         cudaFuncAttributeMaxDynamicSharedMemorySize, 2 * STAGE_BYTES);
    cudaFuncSetAttribute(gemm_f16s<1>,
                         cudaFuncAttributeMaxDynamicSharedMemorySize, 2 * STAGE_BYTES);

    // preps
    split_fp16<<<(BT * CDIM / 4) / 256, 256>>>(
        (const float4*)x, (__half2*)xh, (__half2*)xl, BT * CDIM / 4);
    conv_fp16<<<(CDIM * QKV_N / 4) / 256, 256>>>(
        (const float4*)w_attn, (__half2*)wah, CDIM * QKV_N / 4);
    conv_fp16<<<(CDIM * CDIM / 4) / 256, 256>>>(
        (const float4*)w_proj, (__half2*)wph, CDIM * CDIM / 4);

    // 1) QKV GEMM: [8192,1024]@[1024,3072] -> fp16 q/k/v
    {
        dim3 grid(QKV_N / 256, BT / 128);   // 12 x 64
        gemm_f16s<1><<<grid, 256, 2 * STAGE_BYTES>>>(xh, xl, wah, nullptr, QKV_N, CDIM);
    }
    // 2) attention (single-pass fp16)
    {
        dim3 grid(SEQ / 128, BATCH * NHEAD);  // 16 x 64
        flash_attn_mma<<<grid, 256>>>();
    }
    // 3) proj GEMM: [8192,1024]@[1024,1024] -> out
    {
        dim3 grid(CDIM / 256, BT / 128);    // 4 x 64
        gemm_f16s<0><<<grid, 256, 2 * STAGE_BYTES>>>(yh, yl, wph, out, CDIM, CDIM);
    }
}

// round 8
// speedup vs baseline: 9.7455x; 1.3112x over previous
#include <cuda_runtime.h>
#include <cuda_fp16.h>
#include <cstddef>
#include <cstdint>

// Problem constants
#define BATCH 4
#define SEQ   2048
#define CDIM  1024
#define NHEAD 16
#define HDIM  64
#define BT    (BATCH*SEQ)       // 8192
#define QKV_N (3*CDIM)          // 3072

// Scratch (device globals; no allocation allowed)
__device__ alignas(16) __half g_q[BATCH*NHEAD*SEQ*HDIM];       // fp16
__device__ alignas(16) __half g_k[BATCH*NHEAD*SEQ*HDIM];
__device__ alignas(16) __half g_v[BATCH*NHEAD*SEQ*HDIM];
__device__ alignas(16) __half g_xh[BT*CDIM];                   // x fp16 [M,K]
__device__ alignas(16) __half g_yh[BT*CDIM], g_yl[BT*CDIM];    // split y [M,K]
__device__ alignas(16) __half g_wah[CDIM*QKV_N];               // w_attn fp16 [K,N]
__device__ alignas(16) __half g_wph[CDIM*CDIM];                // w_proj fp16 [K,N]

// ---------------------------------------------------------------------------
// Helpers
// ---------------------------------------------------------------------------
__device__ __forceinline__ uint32_t smem_u32(const void* p) {
    return (uint32_t)__cvta_generic_to_shared(p);
}
__device__ __forceinline__ void mma16816(float* c, const uint32_t* a,
                                         uint32_t b0, uint32_t b1) {
    asm volatile(
        "mma.sync.aligned.m16n8k16.row.col.f32.f16.f16.f32 "
        "{%0,%1,%2,%3},{%4,%5,%6,%7},{%8,%9},{%0,%1,%2,%3};"
        : "+f"(c[0]), "+f"(c[1]), "+f"(c[2]), "+f"(c[3])
        : "r"(a[0]), "r"(a[1]), "r"(a[2]), "r"(a[3]), "r"(b0), "r"(b1));
}
__device__ __forceinline__ void ldmx4(uint32_t* r, uint32_t addr) {
    asm volatile("ldmatrix.sync.aligned.m8n8.x4.shared.b16 {%0,%1,%2,%3},[%4];"
                 : "=r"(r[0]), "=r"(r[1]), "=r"(r[2]), "=r"(r[3]) : "r"(addr));
}
__device__ __forceinline__ void ldmx2(uint32_t& r0, uint32_t& r1, uint32_t addr) {
    asm volatile("ldmatrix.sync.aligned.m8n8.x2.shared.b16 {%0,%1},[%2];"
                 : "=r"(r0), "=r"(r1) : "r"(addr));
}
__device__ __forceinline__ void ldmx2t(uint32_t& r0, uint32_t& r1, uint32_t addr) {
    asm volatile("ldmatrix.sync.aligned.m8n8.x2.trans.shared.b16 {%0,%1},[%2];"
                 : "=r"(r0), "=r"(r1) : "r"(addr));
}
__device__ __forceinline__ void cp16(uint32_t saddr, const void* g) {
    asm volatile("cp.async.cg.shared.global [%0], [%1], 16;" :: "r"(saddr), "l"(g));
}
__device__ __forceinline__ void cp_commit() { asm volatile("cp.async.commit_group;"); }
template<int Np> __device__ __forceinline__ void cp_wait() {
    asm volatile("cp.async.wait_group %0;" :: "n"(Np));
}
__device__ __forceinline__ void split2h(__half2* hp, __half2* lp,
                                        float x0, float x1) {
    __half h0 = __float2half_rn(x0);
    __half h1 = __float2half_rn(x1);
    *hp = __halves2half2(h0, h1);
    *lp = __halves2half2(__float2half_rn(x0 - __half2float(h0)),
                         __float2half_rn(x1 - __half2float(h1)));
}

// ---------------------------------------------------------------------------
// Prep: fp32 -> fp16
// ---------------------------------------------------------------------------
__global__ __launch_bounds__(256) void conv_fp16(
    const float4* __restrict__ in, __half2* __restrict__ h, int n4)
{
    int i = blockIdx.x * 256 + threadIdx.x;
    if (i >= n4) return;
    float4 v = in[i];
    h[i * 2]     = __floats2half2_rn(v.x, v.y);
    h[i * 2 + 1] = __floats2half2_rn(v.z, v.w);
}

// ---------------------------------------------------------------------------
// fp16 GEMM: C[M,N] = A[M,K] @ B[K,N]  (SPLIT=1: A = Ah+Al, 2 MMA passes)
// 128x128 tile, BK=32, 8 warps (warp tile 64x32), cp.async double-buffered,
// XOR-swizzled smem. EPI=0: fp32 C. EPI=1: QKV scatter as fp16 q/k/v.
// ---------------------------------------------------------------------------
template<int EPI, int SPLIT>
__global__ __launch_bounds__(256)
void gemm_f16s(const __half* __restrict__ Ah, const __half* __restrict__ Al,
               const __half* __restrict__ Bh,
               float* __restrict__ C, int N, int K)
{
    constexpr uint32_t SB_BYTES = SPLIT ? 24576 : 16384;  // Ah | (Al) | Bh
    constexpr uint32_t BOFF     = SPLIT ? 16384 : 8192;

    extern __shared__ char smem[];
    const uint32_t sbase = smem_u32(smem);

    const int t = threadIdx.x, lane = t & 31, w = t >> 5;
    const int m0 = blockIdx.y * 128, n0 = blockIdx.x * 128;
    const int wm = w & 1, wn = w >> 1;

    float acc[4][4][4] = {};
    const int NIT = K / 32;

    auto load_stage = [&](int it, int buf) {
        uint32_t sb = sbase + buf * SB_BYTES;
        int k0 = it * 32;
        #pragma unroll
        for (int u = 0; u < 2; ++u) {
            int q = t + u * 256;
            int r = q >> 2, c16 = q & 3;
            uint32_t sc = (uint32_t)(r * 4 + (c16 ^ ((r >> 1) & 3))) * 16;
            size_t go = (size_t)(m0 + r) * K + k0 + c16 * 8;
            cp16(sb + sc, Ah + go);
            if (SPLIT) cp16(sb + 8192 + sc, Al + go);
        }
        #pragma unroll
        for (int u = 0; u < 2; ++u) {
            int q = t + u * 256;
            int k = q >> 4, c16 = q & 15;
            uint32_t sc = (uint32_t)(k * 16 + (c16 ^ (k & 7))) * 16;
            size_t go = (size_t)(k0 + k) * N + n0 + c16 * 8;
            cp16(sb + BOFF + sc, Bh + go);
        }
    };

    load_stage(0, 0);
    cp_commit();

    for (int it = 0; it < NIT; ++it) {
        if (it + 1 < NIT) {
            load_stage(it + 1, (it + 1) & 1);
            cp_commit();
            cp_wait<1>();
        } else {
            cp_wait<0>();
        }
        __syncthreads();

        uint32_t sb  = sbase + (it & 1) * SB_BYTES;
        uint32_t sAh = sb, sAl = sb + 8192, sBh = sb + BOFF;

        #pragma unroll
        for (int kk = 0; kk < 2; ++kk) {
            uint32_t ar[4][4], bf[4][2];
            uint32_t offA[4];
            #pragma unroll
            for (int mt = 0; mt < 4; ++mt) {
                int r = wm * 64 + mt * 16 + (lane & 15);
                int c16 = kk * 2 + (lane >> 4);
                offA[mt] = (uint32_t)(r * 4 + (c16 ^ ((r >> 1) & 3))) * 16;
                ldmx4(ar[mt], sAh + offA[mt]);
            }
            #pragma unroll
            for (int nt = 0; nt < 4; ++nt) {
                int k = kk * 16 + (lane & 15);
                int c16 = wn * 4 + nt;
                uint32_t off = (uint32_t)(k * 16 + (c16 ^ (k & 7))) * 16;
                ldmx2t(bf[nt][0], bf[nt][1], sBh + off);
            }
            #pragma unroll
            for (int mt = 0; mt < 4; ++mt)
                #pragma unroll
                for (int nt = 0; nt < 4; ++nt)
                    mma16816(acc[mt][nt], ar[mt], bf[nt][0], bf[nt][1]);
            if (SPLIT) {
                #pragma unroll
                for (int mt = 0; mt < 4; ++mt)
                    ldmx4(ar[mt], sAl + offA[mt]);
                #pragma unroll
                for (int mt = 0; mt < 4; ++mt)
                    #pragma unroll
                    for (int nt = 0; nt < 4; ++nt)
                        mma16816(acc[mt][nt], ar[mt], bf[nt][0], bf[nt][1]);
            }
        }
        __syncthreads();
    }

    // epilogue
    int g = lane >> 2, qoff = (lane & 3) * 2;
    if (EPI == 0) {
        #pragma unroll
        for (int mt = 0; mt < 4; ++mt) {
            int r0 = m0 + wm * 64 + mt * 16 + g;
            #pragma unroll
            for (int nt = 0; nt < 4; ++nt) {
                int n = n0 + wn * 32 + nt * 8 + qoff;
                *(float2*)(C + (size_t)r0 * N + n) =
                    make_float2(acc[mt][nt][0], acc[mt][nt][1]);
                *(float2*)(C + (size_t)(r0 + 8) * N + n) =
                    make_float2(acc[mt][nt][2], acc[mt][nt][3]);
            }
        }
    } else {
        // warp's 32-col slice lies in one region & head
        int n_first = n0 + wn * 32;
        int region = n_first >> 10;
        int h = (n_first & 1023) >> 6;
        int dbase = n_first & 63;                 // 0 or 32
        __half* dst = (region == 0) ? g_q : (region == 1) ? g_k : g_v;
        #pragma unroll
        for (int mt = 0; mt < 4; ++mt) {
            int r = m0 + wm * 64 + mt * 16 + g;
            int b = r >> 11, tt = r & 2047;
            size_t base = ((size_t)(b * NHEAD + h) * SEQ + tt) * HDIM;
            #pragma unroll
            for (int nt = 0; nt < 4; ++nt) {
                int d = dbase + nt * 8 + qoff;
                *(__half2*)(dst + base + d) =
                    __floats2half2_rn(acc[mt][nt][0], acc[mt][nt][1]);
                *(__half2*)(dst + base + 8 * HDIM + d) =
                    __floats2half2_rn(acc[mt][nt][2], acc[mt][nt][3]);
            }
        }
    }
}

// ---------------------------------------------------------------------------
// Flash attention, single-pass fp16 (validated round 7).
// Double-buffered cp.async K/V tiles. Writes y as split fp16 hi/lo.
// ---------------------------------------------------------------------------
#define LDK 72                  // padded smem row (fp16 elems)
#define ABUF 9216               // bytes per 64xLDK fp16 array
#define KVTILE (2*ABUF)         // kh | vh

__global__ __launch_bounds__(256) void flash_attn_mma()
{
    __shared__ char sm[2 * KVTILE];       // 36,864 B (Q staged here first)
    const uint32_t smb = smem_u32(sm);

    int t = threadIdx.x, lane = t & 31, w = t >> 5;
    int bx = blockIdx.x, bh2 = blockIdx.y;
    int b = bh2 >> 4, h = bh2 & 15;

    size_t headoff = (size_t)bh2 * SEQ * HDIM;

    // ---- stage Q tile (128x64)
    {
        const __half* qg = g_q + headoff + (size_t)bx * 128 * HDIM;
        #pragma unroll
        for (int i = 0; i < 4; ++i) {
            int q = t + i * 256;
            int r = q >> 3, c8 = q & 7;
            uint32_t soff = (uint32_t)(r * LDK + c8 * 8) * 2;
            cp16(smb + soff, qg + r * 64 + c8 * 8);
        }
    }
    cp_commit();
    cp_wait<0>();
    __syncthreads();

    uint32_t qf[4][4];
    {
        int row = w * 16 + (lane & 15);
        #pragma unroll
        for (int kt = 0; kt < 4; ++kt) {
            int col = kt * 16 + (lane >> 4) * 8;
            ldmx4(qf[kt], smb + (uint32_t)(row * LDK + col) * 2);
        }
    }
    __syncthreads();

    float oacc[8][4];
    #pragma unroll
    for (int i = 0; i < 8; ++i) { oacc[i][0]=0.f; oacc[i][1]=0.f; oacc[i][2]=0.f; oacc[i][3]=0.f; }

    float m0 = -1e30f, m1 = -1e30f, l0 = 0.f, l1 = 0.f;
    int g    = lane >> 2;
    int qoff = (lane & 3) * 2;
    int rw   = bx * 128 + w * 16;
    const float scale = 0.125f;

    auto load_kv = [&](int kt, int buf) {
        size_t tb = headoff + (size_t)kt * 64 * HDIM;
        uint32_t bb = smb + buf * KVTILE;
        #pragma unroll
        for (int i = 0; i < 2; ++i) {
            int q = t + i * 256;
            int r = q >> 3, c8 = q & 7;
            uint32_t soff = (uint32_t)(r * LDK + c8 * 8) * 2;
            size_t go = tb + r * 64 + c8 * 8;
            cp16(bb + soff,        g_k + go);
            cp16(bb + ABUF + soff, g_v + go);
        }
    };

    int ntiles = 2 * bx + 2;
    load_kv(0, 0);
    cp_commit();

    for (int kt = 0; kt < ntiles; ++kt) {
        if (kt + 1 < ntiles) {
            load_kv(kt + 1, (kt + 1) & 1);
            cp_commit();
            cp_wait<1>();
        } else {
            cp_wait<0>();
        }
        __syncthreads();

        uint32_t bb = smb + (kt & 1) * KVTILE;

        if (kt * 64 <= rw + 15) {
            // ---- S = Q K^T
            float sacc[8][4];
            #pragma unroll
            for (int i = 0; i < 8; ++i) { sacc[i][0]=0.f; sacc[i][1]=0.f; sacc[i][2]=0.f; sacc[i][3]=0.f; }

            #pragma unroll
            for (int c = 0; c < 4; ++c) {
                int col = c * 16 + (((lane & 15) >> 3)) * 8;
                int keyrb = lane & 7;
                uint32_t kf[8][2];
                #pragma unroll
                for (int nt = 0; nt < 8; ++nt)
                    ldmx2(kf[nt][0], kf[nt][1],
                          bb + (uint32_t)((nt * 8 + keyrb) * LDK + col) * 2);
                #pragma unroll
                for (int nt = 0; nt < 8; ++nt)
                    mma16816(sacc[nt], qf[c], kf[nt][0], kf[nt][1]);
            }

            // ---- scale + causal mask + row max
            int i0 = rw + g, i1 = rw + g + 8;
            float mt0 = -1e30f, mt1 = -1e30f;
            #pragma unroll
            for (int nt = 0; nt < 8; ++nt) {
                int j0 = kt * 64 + nt * 8 + qoff;
                float s0 = sacc[nt][0] * scale;
                float s1 = sacc[nt][1] * scale;
                float s2 = sacc[nt][2] * scale;
                float s3 = sacc[nt][3] * scale;
                if (j0     > i0) s0 = -1e30f;
                if (j0 + 1 > i0) s1 = -1e30f;
                if (j0     > i1) s2 = -1e30f;
                if (j0 + 1 > i1) s3 = -1e30f;
                sacc[nt][0] = s0; sacc[nt][1] = s1;
                sacc[nt][2] = s2; sacc[nt][3] = s3;
                mt0 = fmaxf(mt0, fmaxf(s0, s1));
                mt1 = fmaxf(mt1, fmaxf(s2, s3));
            }
            mt0 = fmaxf(mt0, __shfl_xor_sync(0xffffffffu, mt0, 1));
            mt0 = fmaxf(mt0, __shfl_xor_sync(0xffffffffu, mt0, 2));
            mt1 = fmaxf(mt1, __shfl_xor_sync(0xffffffffu, mt1, 1));
            mt1 = fmaxf(mt1, __shfl_xor_sync(0xffffffffu, mt1, 2));

            float mn0 = fmaxf(m0, mt0), mn1 = fmaxf(m1, mt1);
            float a0 = __expf(m0 - mn0), a1 = __expf(m1 - mn1);
            m0 = mn0; m1 = mn1;
            l0 *= a0;  l1 *= a1;
            #pragma unroll
            for (int nt = 0; nt < 8; ++nt) {
                oacc[nt][0] *= a0; oacc[nt][1] *= a0;
                oacc[nt][2] *= a1; oacc[nt][3] *= a1;
            }

            // ---- P = exp(S - m), O += P V
            #pragma unroll
            for (int c2 = 0; c2 < 4; ++c2) {
                float p0 = __expf(sacc[2*c2  ][0] - m0);
                float p1 = __expf(sacc[2*c2  ][1] - m0);
                float p2 = __expf(sacc[2*c2  ][2] - m1);
                float p3 = __expf(sacc[2*c2  ][3] - m1);
                float p4 = __expf(sacc[2*c2+1][0] - m0);
                float p5 = __expf(sacc[2*c2+1][1] - m0);
                float p6 = __expf(sacc[2*c2+1][2] - m1);
                float p7 = __expf(sacc[2*c2+1][3] - m1);
                l0 += p0 + p1 + p4 + p5;
                l1 += p2 + p3 + p6 + p7;

                uint32_t pr[4];
                {
                    __half2 hp;
                    hp = __floats2half2_rn(p0, p1); pr[0] = *(uint32_t*)&hp;
                    hp = __floats2half2_rn(p2, p3); pr[1] = *(uint32_t*)&hp;
                    hp = __floats2half2_rn(p4, p5); pr[2] = *(uint32_t*)&hp;
                    hp = __floats2half2_rn(p6, p7); pr[3] = *(uint32_t*)&hp;
                }

                int keyr = c2 * 16 + (lane & 15);
                uint32_t vf[8][2];
                #pragma unroll
                for (int nt = 0; nt < 8; ++nt)
                    ldmx2t(vf[nt][0], vf[nt][1],
                           bb + ABUF + (uint32_t)(keyr * LDK + nt * 8) * 2);
                #pragma unroll
                for (int nt = 0; nt < 8; ++nt)
                    mma16816(oacc[nt], pr, vf[nt][0], vf[nt][1]);
            }
        }
        __syncthreads();
    }

    // ---- finalize: write y as split fp16 (proj A needs hi/lo)
    l0 += __shfl_xor_sync(0xffffffffu, l0, 1);
    l0 += __shfl_xor_sync(0xffffffffu, l0, 2);
    l1 += __shfl_xor_sync(0xffffffffu, l1, 1);
    l1 += __shfl_xor_sync(0xffffffffu, l1, 2);
    float inv0 = 1.f / l0, inv1 = 1.f / l1;

    size_t o0 = ((size_t)(b * SEQ + rw + g    )) * CDIM + h * 64;
    size_t o1 = ((size_t)(b * SEQ + rw + g + 8)) * CDIM + h * 64;
    #pragma unroll
    for (int nt = 0; nt < 8; ++nt) {
        __half2 hp, lp;
        split2h(&hp, &lp, oacc[nt][0] * inv0, oacc[nt][1] * inv0);
        *(__half2*)(g_yh + o0 + nt * 8 + qoff) = hp;
        *(__half2*)(g_yl + o0 + nt * 8 + qoff) = lp;
        split2h(&hp, &lp, oacc[nt][2] * inv1, oacc[nt][3] * inv1);
        *(__half2*)(g_yh + o1 + nt * 8 + qoff) = hp;
        *(__half2*)(g_yl + o1 + nt * 8 + qoff) = lp;
    }
}

// ---------------------------------------------------------------------------
// Launch: preps -> QKV GEMM (single-pass) -> attention -> proj GEMM (split)
// ---------------------------------------------------------------------------
extern "C" void kernel_launch(void* const* d_in, const int* in_sizes, int n_in,
                              void* d_out, int out_size)
{
    const float* x      = (const float*)d_in[0];
    const float* w_attn = (const float*)d_in[1];
    const float* w_proj = (const float*)d_in[2];
    float* out = (float*)d_out;

    __half *xh, *yh, *yl, *wah, *wph;
    cudaGetSymbolAddress((void**)&xh,  g_xh);
    cudaGetSymbolAddress((void**)&yh,  g_yh);  cudaGetSymbolAddress((void**)&yl,  g_yl);
    cudaGetSymbolAddress((void**)&wah, g_wah); cudaGetSymbolAddress((void**)&wph, g_wph);

    cudaFuncSetAttribute((const void*)gemm_f16s<1,0>,
                         cudaFuncAttributeMaxDynamicSharedMemorySize, 2 * 16384);
    cudaFuncSetAttribute((const void*)gemm_f16s<0,1>,
                         cudaFuncAttributeMaxDynamicSharedMemorySize, 2 * 24576);

    // preps (plain fp16 converts)
    conv_fp16<<<(BT * CDIM / 4) / 256, 256>>>(
        (const float4*)x, (__half2*)xh, BT * CDIM / 4);
    conv_fp16<<<(CDIM * QKV_N / 4) / 256, 256>>>(
        (const float4*)w_attn, (__half2*)wah, CDIM * QKV_N / 4);
    conv_fp16<<<(CDIM * CDIM / 4) / 256, 256>>>(
        (const float4*)w_proj, (__half2*)wph, CDIM * CDIM / 4);

    // 1) QKV GEMM (single-pass fp16): [8192,1024]@[1024,3072] -> fp16 q/k/v
    {
        dim3 grid(QKV_N / 128, BT / 128);   // 24 x 64
        gemm_f16s<1,0><<<grid, 256, 2 * 16384>>>(xh, nullptr, wah, nullptr, QKV_N, CDIM);
    }
    // 2) attention (single-pass fp16)
    {
        dim3 grid(SEQ / 128, BATCH * NHEAD);  // 16 x 64
        flash_attn_mma<<<grid, 256>>>();
    }
    // 3) proj GEMM (split-A 2-pass): [8192,1024]@[1024,1024] -> fp32 out
    {
        dim3 grid(CDIM / 128, BT / 128);    // 8 x 64
        gemm_f16s<0,1><<<grid, 256, 2 * 24576>>>(yh, yl, wph, out, CDIM, CDIM);
    }
}

// round 11
// speedup vs baseline: 11.5267x; 1.1828x over previous
#include <cuda_runtime.h>
#include <cuda_fp16.h>
#include <cstddef>
#include <cstdint>

// Problem constants
#define BATCH 4
#define SEQ   2048
#define CDIM  1024
#define NHEAD 16
#define HDIM  64
#define BT    (BATCH*SEQ)       // 8192
#define QKV_N (3*CDIM)          // 3072

// Scratch (device globals; no allocation allowed)
__device__ alignas(16) __half g_q[BATCH*NHEAD*SEQ*HDIM];       // fp16
__device__ alignas(16) __half g_k[BATCH*NHEAD*SEQ*HDIM];
__device__ alignas(16) __half g_v[BATCH*NHEAD*SEQ*HDIM];
__device__ alignas(16) __half g_xh[BT*CDIM];                   // x fp16 [M,K]
__device__ alignas(16) __half g_yh[BT*CDIM];                   // y fp16 [M,K]
__device__ alignas(16) __half g_wah[CDIM*QKV_N];               // w_attn fp16 [K,N]
__device__ alignas(16) __half g_wph[CDIM*CDIM];                // w_proj fp16 [K,N]

// ---------------------------------------------------------------------------
// Helpers
// ---------------------------------------------------------------------------
__device__ __forceinline__ uint32_t smem_u32(const void* p) {
    return (uint32_t)__cvta_generic_to_shared(p);
}
__device__ __forceinline__ void mma16816(float* c, const uint32_t* a,
                                         uint32_t b0, uint32_t b1) {
    asm volatile(
        "mma.sync.aligned.m16n8k16.row.col.f32.f16.f16.f32 "
        "{%0,%1,%2,%3},{%4,%5,%6,%7},{%8,%9},{%0,%1,%2,%3};"
        : "+f"(c[0]), "+f"(c[1]), "+f"(c[2]), "+f"(c[3])
        : "r"(a[0]), "r"(a[1]), "r"(a[2]), "r"(a[3]), "r"(b0), "r"(b1));
}
__device__ __forceinline__ void ldmx4(uint32_t* r, uint32_t addr) {
    asm volatile("ldmatrix.sync.aligned.m8n8.x4.shared.b16 {%0,%1,%2,%3},[%4];"
                 : "=r"(r[0]), "=r"(r[1]), "=r"(r[2]), "=r"(r[3]) : "r"(addr));
}
__device__ __forceinline__ void ldmx2(uint32_t& r0, uint32_t& r1, uint32_t addr) {
    asm volatile("ldmatrix.sync.aligned.m8n8.x2.shared.b16 {%0,%1},[%2];"
                 : "=r"(r0), "=r"(r1) : "r"(addr));
}
__device__ __forceinline__ void ldmx2t(uint32_t& r0, uint32_t& r1, uint32_t addr) {
    asm volatile("ldmatrix.sync.aligned.m8n8.x2.trans.shared.b16 {%0,%1},[%2];"
                 : "=r"(r0), "=r"(r1) : "r"(addr));
}
__device__ __forceinline__ void cp16(uint32_t saddr, const void* g) {
    asm volatile("cp.async.cg.shared.global [%0], [%1], 16;" :: "r"(saddr), "l"(g));
}
__device__ __forceinline__ void cp_commit() { asm volatile("cp.async.commit_group;"); }
template<int Np> __device__ __forceinline__ void cp_wait() {
    asm volatile("cp.async.wait_group %0;" :: "n"(Np));
}

// ---------------------------------------------------------------------------
// Prep: fused fp32 -> fp16 conversion of x, w_attn, w_proj (one launch)
// ---------------------------------------------------------------------------
#define N4_X  (BT*CDIM/4)          // 2,097,152
#define N4_WA (CDIM*QKV_N/4)       //   786,432
#define N4_WP (CDIM*CDIM/4)        //   262,144
#define N4_TOT (N4_X + N4_WA + N4_WP)

__global__ __launch_bounds__(256) void conv_all(
    const float4* __restrict__ x, const float4* __restrict__ wa,
    const float4* __restrict__ wp,
    __half2* __restrict__ xh, __half2* __restrict__ wah,
    __half2* __restrict__ wph)
{
    int i = blockIdx.x * 256 + threadIdx.x;
    if (i >= N4_TOT) return;
    const float4* src;
    __half2* dst;
    int j;
    if (i < N4_X)               { src = x;  dst = xh;  j = i; }
    else if (i < N4_X + N4_WA)  { src = wa; dst = wah; j = i - N4_X; }
    else                        { src = wp; dst = wph; j = i - N4_X - N4_WA; }
    float4 v = src[j];
    dst[j * 2]     = __floats2half2_rn(v.x, v.y);
    dst[j * 2 + 1] = __floats2half2_rn(v.z, v.w);
}

// ---------------------------------------------------------------------------
// fp16 GEMM: C[M,N] = A[M,K] @ B[K,N], single-pass.
// 128x128 tile, BK=32, 8 warps (warp tile 64x32), cp.async double-buffered,
// XOR-swizzled smem. EPI=0: fp32 C. EPI=1: QKV scatter as fp16 q/k/v.
// ---------------------------------------------------------------------------
#define SB_BYTES 16384u   // Ah(8K) | Bh(8K)

template<int EPI>
__global__ __launch_bounds__(256)
void gemm_f16(const __half* __restrict__ Ah, const __half* __restrict__ Bh,
              float* __restrict__ C, int N, int K)
{
    extern __shared__ char smem[];
    const uint32_t sbase = smem_u32(smem);

    const int t = threadIdx.x, lane = t & 31, w = t >> 5;
    const int m0 = blockIdx.y * 128, n0 = blockIdx.x * 128;
    const int wm = w & 1, wn = w >> 1;

    float acc[4][4][4] = {};
    const int NIT = K / 32;

    auto load_stage = [&](int it, int buf) {
        uint32_t sb = sbase + buf * SB_BYTES;
        int k0 = it * 32;
        #pragma unroll
        for (int u = 0; u < 2; ++u) {
            int q = t + u * 256;
            int r = q >> 2, c16 = q & 3;
            uint32_t sc = (uint32_t)(r * 4 + (c16 ^ ((r >> 1) & 3))) * 16;
            cp16(sb + sc, Ah + (size_t)(m0 + r) * K + k0 + c16 * 8);
        }
        #pragma unroll
        for (int u = 0; u < 2; ++u) {
            int q = t + u * 256;
            int k = q >> 4, c16 = q & 15;
            uint32_t sc = (uint32_t)(k * 16 + (c16 ^ (k & 7))) * 16;
            cp16(sb + 8192 + sc, Bh + (size_t)(k0 + k) * N + n0 + c16 * 8);
        }
    };

    load_stage(0, 0);
    cp_commit();

    for (int it = 0; it < NIT; ++it) {
        if (it + 1 < NIT) {
            load_stage(it + 1, (it + 1) & 1);
            cp_commit();
            cp_wait<1>();
        } else {
            cp_wait<0>();
        }
        __syncthreads();

        uint32_t sb  = sbase + (it & 1) * SB_BYTES;
        uint32_t sAh = sb, sBh = sb + 8192;

        #pragma unroll
        for (int kk = 0; kk < 2; ++kk) {
            uint32_t ar[4][4], bf[4][2];
            #pragma unroll
            for (int mt = 0; mt < 4; ++mt) {
                int r = wm * 64 + mt * 16 + (lane & 15);
                int c16 = kk * 2 + (lane >> 4);
                uint32_t off = (uint32_t)(r * 4 + (c16 ^ ((r >> 1) & 3))) * 16;
                ldmx4(ar[mt], sAh + off);
            }
            #pragma unroll
            for (int nt = 0; nt < 4; ++nt) {
                int k = kk * 16 + (lane & 15);
                int c16 = wn * 4 + nt;
                uint32_t off = (uint32_t)(k * 16 + (c16 ^ (k & 7))) * 16;
                ldmx2t(bf[nt][0], bf[nt][1], sBh + off);
            }
            #pragma unroll
            for (int mt = 0; mt < 4; ++mt)
                #pragma unroll
                for (int nt = 0; nt < 4; ++nt)
                    mma16816(acc[mt][nt], ar[mt], bf[nt][0], bf[nt][1]);
        }
        __syncthreads();
    }

    // epilogue
    int g = lane >> 2, qoff = (lane & 3) * 2;
    if (EPI == 0) {
        #pragma unroll
        for (int mt = 0; mt < 4; ++mt) {
            int r0 = m0 + wm * 64 + mt * 16 + g;
            #pragma unroll
            for (int nt = 0; nt < 4; ++nt) {
                int n = n0 + wn * 32 + nt * 8 + qoff;
                *(float2*)(C + (size_t)r0 * N + n) =
                    make_float2(acc[mt][nt][0], acc[mt][nt][1]);
                *(float2*)(C + (size_t)(r0 + 8) * N + n) =
                    make_float2(acc[mt][nt][2], acc[mt][nt][3]);
            }
        }
    } else {
        int n_first = n0 + wn * 32;
        int region = n_first >> 10;
        int h = (n_first & 1023) >> 6;
        int dbase = n_first & 63;                 // 0 or 32
        __half* dst = (region == 0) ? g_q : (region == 1) ? g_k : g_v;
        #pragma unroll
        for (int mt = 0; mt < 4; ++mt) {
            int r = m0 + wm * 64 + mt * 16 + g;
            int b = r >> 11, tt = r & 2047;
            size_t base = ((size_t)(b * NHEAD + h) * SEQ + tt) * HDIM;
            #pragma unroll
            for (int nt = 0; nt < 4; ++nt) {
                int d = dbase + nt * 8 + qoff;
                *(__half2*)(dst + base + d) =
                    __floats2half2_rn(acc[mt][nt][0], acc[mt][nt][1]);
                *(__half2*)(dst + base + 8 * HDIM + d) =
                    __floats2half2_rn(acc[mt][nt][2], acc[mt][nt][3]);
            }
        }
    }
}

// ---------------------------------------------------------------------------
// Flash attention, single-pass fp16. Heavy CTAs scheduled first (bx flipped).
// Double-buffered cp.async K/V tiles. Writes y as fp16.
// ---------------------------------------------------------------------------
#define LDK 72                  // padded smem row (fp16 elems)
#define ABUF 9216               // bytes per 64xLDK fp16 array
#define KVTILE (2*ABUF)         // kh | vh

__global__ __launch_bounds__(256) void flash_attn_mma()
{
    __shared__ char sm[2 * KVTILE];       // 36,864 B (Q staged here first)
    const uint32_t smb = smem_u32(sm);

    int t = threadIdx.x, lane = t & 31, w = t >> 5;
    int bx = (gridDim.x - 1) - blockIdx.x;        // heavy blocks first
    int bh2 = blockIdx.y;
    int b = bh2 >> 4, h = bh2 & 15;

    size_t headoff = (size_t)bh2 * SEQ * HDIM;

    // ---- stage Q tile (128x64)
    {
        const __half* qg = g_q + headoff + (size_t)bx * 128 * HDIM;
        #pragma unroll
        for (int i = 0; i < 4; ++i) {
            int q = t + i * 256;
            int r = q >> 3, c8 = q & 7;
            uint32_t soff = (uint32_t)(r * LDK + c8 * 8) * 2;
            cp16(smb + soff, qg + r * 64 + c8 * 8);
        }
    }
    cp_commit();
    cp_wait<0>();
    __syncthreads();

    uint32_t qf[4][4];
    {
        int row = w * 16 + (lane & 15);
        #pragma unroll
        for (int kt = 0; kt < 4; ++kt) {
            int col = kt * 16 + (lane >> 4) * 8;
            ldmx4(qf[kt], smb + (uint32_t)(row * LDK + col) * 2);
        }
    }
    __syncthreads();

    float oacc[8][4];
    #pragma unroll
    for (int i = 0; i < 8; ++i) { oacc[i][0]=0.f; oacc[i][1]=0.f; oacc[i][2]=0.f; oacc[i][3]=0.f; }

    float m0 = -1e30f, m1 = -1e30f, l0 = 0.f, l1 = 0.f;
    int g    = lane >> 2;
    int qoff = (lane & 3) * 2;
    int rw   = bx * 128 + w * 16;
    const float scale = 0.125f;

    auto load_kv = [&](int kt, int buf) {
        size_t tb = headoff + (size_t)kt * 64 * HDIM;
        uint32_t bb = smb + buf * KVTILE;
        #pragma unroll
        for (int i = 0; i < 2; ++i) {
            int q = t + i * 256;
            int r = q >> 3, c8 = q & 7;
            uint32_t soff = (uint32_t)(r * LDK + c8 * 8) * 2;
            size_t go = tb + r * 64 + c8 * 8;
            cp16(bb + soff,        g_k + go);
            cp16(bb + ABUF + soff, g_v + go);
        }
    };

    int ntiles = 2 * bx + 2;
    load_kv(0, 0);
    cp_commit();

    for (int kt = 0; kt < ntiles; ++kt) {
        if (kt + 1 < ntiles) {
            load_kv(kt + 1, (kt + 1) & 1);
            cp_commit();
            cp_wait<1>();
        } else {
            cp_wait<0>();
        }
        __syncthreads();

        uint32_t bb = smb + (kt & 1) * KVTILE;

        if (kt * 64 <= rw + 15) {
            // ---- S = Q K^T
            float sacc[8][4];
            #pragma unroll
            for (int i = 0; i < 8; ++i) { sacc[i][0]=0.f; sacc[i][1]=0.f; sacc[i][2]=0.f; sacc[i][3]=0.f; }

            #pragma unroll
            for (int c = 0; c < 4; ++c) {
                int col = c * 16 + (((lane & 15) >> 3)) * 8;
                int keyrb = lane & 7;
                uint32_t kf[8][2];
                #pragma unroll
                for (int nt = 0; nt < 8; ++nt)
                    ldmx2(kf[nt][0], kf[nt][1],
                          bb + (uint32_t)((nt * 8 + keyrb) * LDK + col) * 2);
                #pragma unroll
                for (int nt = 0; nt < 8; ++nt)
                    mma16816(sacc[nt], qf[c], kf[nt][0], kf[nt][1]);
            }

            // ---- scale + causal mask + row max
            int i0 = rw + g, i1 = rw + g + 8;
            float mt0 = -1e30f, mt1 = -1e30f;
            #pragma unroll
            for (int nt = 0; nt < 8; ++nt) {
                int j0 = kt * 64 + nt * 8 + qoff;
                float s0 = sacc[nt][0] * scale;
                float s1 = sacc[nt][1] * scale;
                float s2 = sacc[nt][2] * scale;
                float s3 = sacc[nt][3] * scale;
                if (j0     > i0) s0 = -1e30f;
                if (j0 + 1 > i0) s1 = -1e30f;
                if (j0     > i1) s2 = -1e30f;
                if (j0 + 1 > i1) s3 = -1e30f;
                sacc[nt][0] = s0; sacc[nt][1] = s1;
                sacc[nt][2] = s2; sacc[nt][3] = s3;
                mt0 = fmaxf(mt0, fmaxf(s0, s1));
                mt1 = fmaxf(mt1, fmaxf(s2, s3));
            }
            mt0 = fmaxf(mt0, __shfl_xor_sync(0xffffffffu, mt0, 1));
            mt0 = fmaxf(mt0, __shfl_xor_sync(0xffffffffu, mt0, 2));
            mt1 = fmaxf(mt1, __shfl_xor_sync(0xffffffffu, mt1, 1));
            mt1 = fmaxf(mt1, __shfl_xor_sync(0xffffffffu, mt1, 2));

            float mn0 = fmaxf(m0, mt0), mn1 = fmaxf(m1, mt1);
            float a0 = __expf(m0 - mn0), a1 = __expf(m1 - mn1);
            m0 = mn0; m1 = mn1;
            l0 *= a0;  l1 *= a1;
            #pragma unroll
            for (int nt = 0; nt < 8; ++nt) {
                oacc[nt][0] *= a0; oacc[nt][1] *= a0;
                oacc[nt][2] *= a1; oacc[nt][3] *= a1;
            }

            // ---- P = exp(S - m), O += P V
            #pragma unroll
            for (int c2 = 0; c2 < 4; ++c2) {
                float p0 = __expf(sacc[2*c2  ][0] - m0);
                float p1 = __expf(sacc[2*c2  ][1] - m0);
                float p2 = __expf(sacc[2*c2  ][2] - m1);
                float p3 = __expf(sacc[2*c2  ][3] - m1);
                float p4 = __expf(sacc[2*c2+1][0] - m0);
                float p5 = __expf(sacc[2*c2+1][1] - m0);
                float p6 = __expf(sacc[2*c2+1][2] - m1);
                float p7 = __expf(sacc[2*c2+1][3] - m1);
                l0 += p0 + p1 + p4 + p5;
                l1 += p2 + p3 + p6 + p7;

                uint32_t pr[4];
                {
                    __half2 hp;
                    hp = __floats2half2_rn(p0, p1); pr[0] = *(uint32_t*)&hp;
                    hp = __floats2half2_rn(p2, p3); pr[1] = *(uint32_t*)&hp;
                    hp = __floats2half2_rn(p4, p5); pr[2] = *(uint32_t*)&hp;
                    hp = __floats2half2_rn(p6, p7); pr[3] = *(uint32_t*)&hp;
                }

                int keyr = c2 * 16 + (lane & 15);
                uint32_t vf[8][2];
                #pragma unroll
                for (int nt = 0; nt < 8; ++nt)
                    ldmx2t(vf[nt][0], vf[nt][1],
                           bb + ABUF + (uint32_t)(keyr * LDK + nt * 8) * 2);
                #pragma unroll
                for (int nt = 0; nt < 8; ++nt)
                    mma16816(oacc[nt], pr, vf[nt][0], vf[nt][1]);
            }
        }
        __syncthreads();
    }

    // ---- finalize: write y as fp16
    l0 += __shfl_xor_sync(0xffffffffu, l0, 1);
    l0 += __shfl_xor_sync(0xffffffffu, l0, 2);
    l1 += __shfl_xor_sync(0xffffffffu, l1, 1);
    l1 += __shfl_xor_sync(0xffffffffu, l1, 2);
    float inv0 = 1.f / l0, inv1 = 1.f / l1;

    size_t o0 = ((size_t)(b * SEQ + rw + g    )) * CDIM + h * 64;
    size_t o1 = ((size_t)(b * SEQ + rw + g + 8)) * CDIM + h * 64;
    #pragma unroll
    for (int nt = 0; nt < 8; ++nt) {
        *(__half2*)(g_yh + o0 + nt * 8 + qoff) =
            __floats2half2_rn(oacc[nt][0] * inv0, oacc[nt][1] * inv0);
        *(__half2*)(g_yh + o1 + nt * 8 + qoff) =
            __floats2half2_rn(oacc[nt][2] * inv1, oacc[nt][3] * inv1);
    }
}

// ---------------------------------------------------------------------------
// Launch: fused prep -> QKV GEMM -> attention -> proj GEMM
// ---------------------------------------------------------------------------
extern "C" void kernel_launch(void* const* d_in, const int* in_sizes, int n_in,
                              void* d_out, int out_size)
{
    const float* x      = (const float*)d_in[0];
    const float* w_attn = (const float*)d_in[1];
    const float* w_proj = (const float*)d_in[2];
    float* out = (float*)d_out;

    __half *xh, *yh, *wah, *wph;
    cudaGetSymbolAddress((void**)&xh,  g_xh);
    cudaGetSymbolAddress((void**)&yh,  g_yh);
    cudaGetSymbolAddress((void**)&wah, g_wah);
    cudaGetSymbolAddress((void**)&wph, g_wph);

    cudaFuncSetAttribute((const void*)gemm_f16<0>,
                         cudaFuncAttributeMaxDynamicSharedMemorySize, 2 * SB_BYTES);
    cudaFuncSetAttribute((const void*)gemm_f16<1>,
                         cudaFuncAttributeMaxDynamicSharedMemorySize, 2 * SB_BYTES);

    // fused fp16 conversion (x, w_attn, w_proj in one launch)
    conv_all<<<(N4_TOT + 255) / 256, 256>>>(
        (const float4*)x, (const float4*)w_attn, (const float4*)w_proj,
        (__half2*)xh, (__half2*)wah, (__half2*)wph);

    // 1) QKV GEMM: [8192,1024]@[1024,3072] -> fp16 q/k/v
    {
        dim3 grid(QKV_N / 128, BT / 128);   // 24 x 64
        gemm_f16<1><<<grid, 256, 2 * SB_BYTES>>>(xh, wah, nullptr, QKV_N, CDIM);
    }
    // 2) attention (single-pass fp16, heavy CTAs first)
    {
        dim3 grid(SEQ / 128, BATCH * NHEAD);  // 16 x 64
        flash_attn_mma<<<grid, 256>>>();
    }
    // 3) proj GEMM (single-pass): [8192,1024]@[1024,1024] -> fp32 out
    {
        dim3 grid(CDIM / 128, BT / 128);    // 8 x 64
        gemm_f16<0><<<grid, 256, 2 * SB_BYTES>>>(yh, wph, out, CDIM, CDIM);
    }
}